// round 2
// baseline (speedup 1.0000x reference)
#include <cuda_runtime.h>
#include <cuda_bf16.h>
#include <cstdint>

// Problem constants
#define H     2048
#define NTOK  2048      // B*S
#define MR    512       // routed intermediate
#define MSH   1024      // shared intermediate
#define NEXP  8
#define NJOBS 9         // 8 routed experts + 1 shared "expert"

// GEMM tiling
#define BM 128
#define BN 64
#define BK 32

// -------- scratch (no mallocs allowed) --------
__device__ int   d_counts[NEXP];
__device__ int   d_tok[NEXP * NTOK];
__device__ float d_wt [NEXP * NTOK];
// per-expert h buffers (2048 slots x 512) + shared (2048 x 1024)
__device__ float d_hbuf[(size_t)NEXP * NTOK * MR + (size_t)NTOK * MSH];

// -------- helpers --------
__device__ __forceinline__ uint32_t f2tf(float x) {
    uint32_t r;
    asm("cvt.rna.tf32.f32 %0, %1;" : "=r"(r) : "f"(x));
    return r;
}

__device__ __forceinline__ void mma_tf32(float* c, const uint32_t* a, const uint32_t* b) {
    asm volatile(
        "mma.sync.aligned.m16n8k8.row.col.f32.tf32.tf32.f32 "
        "{%0,%1,%2,%3}, {%4,%5,%6,%7}, {%8,%9}, {%0,%1,%2,%3};\n"
        : "+f"(c[0]), "+f"(c[1]), "+f"(c[2]), "+f"(c[3])
        : "r"(a[0]), "r"(a[1]), "r"(a[2]), "r"(a[3]),
          "r"(b[0]), "r"(b[1]));
}

// -------- kernel 0: zero output + routing counts --------
__global__ void zero_kernel(float* __restrict__ y) {
    size_t i = (size_t)blockIdx.x * blockDim.x + threadIdx.x;
    reinterpret_cast<float4*>(y)[i] = make_float4(0.f, 0.f, 0.f, 0.f);
    if (i < NEXP) d_counts[i] = 0;
}

// -------- kernel 1: gate logits + top2 + softmax + route lists --------
__global__ void gate_kernel(const float* __restrict__ x, const float* __restrict__ gw) {
    int warp = blockIdx.x * (blockDim.x >> 5) + (threadIdx.x >> 5);
    int lane = threadIdx.x & 31;
    if (warp >= NTOK) return;
    int t = warp;
    const float4* x4 = reinterpret_cast<const float4*>(x + (size_t)t * H);
    const float4* g4 = reinterpret_cast<const float4*>(gw);
    float acc[NEXP];
#pragma unroll
    for (int e = 0; e < NEXP; e++) acc[e] = 0.f;
    for (int i = lane; i < H / 4; i += 32) {
        float4 xv = x4[i];
#pragma unroll
        for (int e = 0; e < NEXP; e++) {
            float4 gv = g4[e * (H / 4) + i];
            acc[e] += xv.x * gv.x + xv.y * gv.y + xv.z * gv.z + xv.w * gv.w;
        }
    }
#pragma unroll
    for (int e = 0; e < NEXP; e++)
#pragma unroll
        for (int o = 16; o; o >>= 1) acc[e] += __shfl_xor_sync(0xffffffffu, acc[e], o);
    if (lane == 0) {
        int i0 = 0; float v0 = acc[0];
#pragma unroll
        for (int e = 1; e < NEXP; e++) if (acc[e] > v0) { v0 = acc[e]; i0 = e; }
        int i1 = -1; float v1 = -1e30f;
#pragma unroll
        for (int e = 0; e < NEXP; e++) if (e != i0 && acc[e] > v1) { v1 = acc[e]; i1 = e; }
        // softmax over the two selected logits (v0 is max)
        float e1 = __expf(v1 - v0);
        float s  = 1.f + e1;
        float w0 = 1.f / s, w1 = e1 / s;
        int p0 = atomicAdd(&d_counts[i0], 1);
        d_tok[i0 * NTOK + p0] = t; d_wt[i0 * NTOK + p0] = w0;
        int p1 = atomicAdd(&d_counts[i1], 1);
        d_tok[i1 * NTOK + p1] = t; d_wt[i1 * NTOK + p1] = w1;
    }
}

// -------- kernel 2: fused gate+up dual-GEMM + SiLU*u epilogue --------
// job 0..7 : routed expert e  (A = gathered x rows, B = Wg[e]/Wu[e], Mdim=512)
// job 8    : shared expert    (A = x identity,     B = sWg/sWu,     Mdim=1024)
__global__ __launch_bounds__(256) void gateup_kernel(
    const float* __restrict__ x,
    const float* __restrict__ Wg, const float* __restrict__ Wu,
    const float* __restrict__ sWg, const float* __restrict__ sWu)
{
    const int  job = blockIdx.z;
    const bool sh  = (job == NEXP);
    const int  Mdim = sh ? MSH : MR;
    const int  cnt  = sh ? NTOK : d_counts[job];
    const int  row0 = blockIdx.y * BM;
    const int  col0 = blockIdx.x * BN;
    if (row0 >= cnt || col0 >= Mdim) return;

    const float* Bg = sh ? sWg : Wg + (size_t)job * H * MR;
    const float* Bu = sh ? sWu : Wu + (size_t)job * H * MR;

    __shared__ uint32_t As[BK][BM + 4];
    __shared__ uint32_t Bs[2][BK][BN + 4];

    const int tid = threadIdx.x;
    const int lane = tid & 31;
    const int wid = tid >> 5;
    const int warp_m = wid & 3;   // 4 warps along M
    const int warp_n = wid >> 2;  // 2 warps along N
    const int g_r = lane >> 2;    // groupID
    const int g_c = lane & 3;     // threadID in group

    // A global load mapping (4 float4/thread): idx -> (row, kquad)
    const float* aptr[4]; int arow[4], akq[4];
#pragma unroll
    for (int i = 0; i < 4; i++) {
        int idx = tid + i * 256;
        int r = idx >> 3, kq = idx & 7;
        arow[i] = r; akq[i] = kq;
        int gl = row0 + r; if (gl >= cnt) gl = cnt - 1;
        int tok = sh ? gl : d_tok[job * NTOK + gl];
        aptr[i] = x + (size_t)tok * H + kq * 4;
    }
    // B global load mapping (2 float4/thread per matrix)
    const float* bpg[2]; const float* bpu[2]; int bkr[2], bnq[2];
#pragma unroll
    for (int i = 0; i < 2; i++) {
        int idx = tid + i * 256;
        int kr = idx >> 4, nq = idx & 15;
        bkr[i] = kr; bnq[i] = nq;
        bpg[i] = Bg + (size_t)kr * Mdim + col0 + nq * 4;
        bpu[i] = Bu + (size_t)kr * Mdim + col0 + nq * 4;
    }

    float accg[2][4][4], accu[2][4][4];
#pragma unroll
    for (int a = 0; a < 2; a++)
#pragma unroll
        for (int b = 0; b < 4; b++)
#pragma unroll
            for (int c = 0; c < 4; c++) { accg[a][b][c] = 0.f; accu[a][b][c] = 0.f; }

    // prefetch iteration 0
    float4 av[4], gv[2], uv[2];
#pragma unroll
    for (int i = 0; i < 4; i++) { av[i] = *reinterpret_cast<const float4*>(aptr[i]); aptr[i] += BK; }
#pragma unroll
    for (int i = 0; i < 2; i++) {
        gv[i] = *reinterpret_cast<const float4*>(bpg[i]); bpg[i] += (size_t)BK * Mdim;
        uv[i] = *reinterpret_cast<const float4*>(bpu[i]); bpu[i] += (size_t)BK * Mdim;
    }

    const int KT = H / BK;
    for (int kt = 0; kt < KT; kt++) {
        __syncthreads();
#pragma unroll
        for (int i = 0; i < 4; i++) {
            As[akq[i] * 4 + 0][arow[i]] = f2tf(av[i].x);
            As[akq[i] * 4 + 1][arow[i]] = f2tf(av[i].y);
            As[akq[i] * 4 + 2][arow[i]] = f2tf(av[i].z);
            As[akq[i] * 4 + 3][arow[i]] = f2tf(av[i].w);
        }
#pragma unroll
        for (int i = 0; i < 2; i++) {
            Bs[0][bkr[i]][bnq[i] * 4 + 0] = f2tf(gv[i].x);
            Bs[0][bkr[i]][bnq[i] * 4 + 1] = f2tf(gv[i].y);
            Bs[0][bkr[i]][bnq[i] * 4 + 2] = f2tf(gv[i].z);
            Bs[0][bkr[i]][bnq[i] * 4 + 3] = f2tf(gv[i].w);
            Bs[1][bkr[i]][bnq[i] * 4 + 0] = f2tf(uv[i].x);
            Bs[1][bkr[i]][bnq[i] * 4 + 1] = f2tf(uv[i].y);
            Bs[1][bkr[i]][bnq[i] * 4 + 2] = f2tf(uv[i].z);
            Bs[1][bkr[i]][bnq[i] * 4 + 3] = f2tf(uv[i].w);
        }
        __syncthreads();

        // issue next iteration's global loads BEFORE the MMAs (latency overlap)
        if (kt + 1 < KT) {
#pragma unroll
            for (int i = 0; i < 4; i++) { av[i] = *reinterpret_cast<const float4*>(aptr[i]); aptr[i] += BK; }
#pragma unroll
            for (int i = 0; i < 2; i++) {
                gv[i] = *reinterpret_cast<const float4*>(bpg[i]); bpg[i] += (size_t)BK * Mdim;
                uv[i] = *reinterpret_cast<const float4*>(bpu[i]); bpu[i] += (size_t)BK * Mdim;
            }
        }

#pragma unroll
        for (int ks = 0; ks < BK / 8; ks++) {
            uint32_t af[2][4], bf[2][4][2];
#pragma unroll
            for (int mf = 0; mf < 2; mf++) {
                int rb = warp_m * 32 + mf * 16 + g_r;
                af[mf][0] = As[ks * 8 + g_c    ][rb    ];
                af[mf][1] = As[ks * 8 + g_c    ][rb + 8];
                af[mf][2] = As[ks * 8 + g_c + 4][rb    ];
                af[mf][3] = As[ks * 8 + g_c + 4][rb + 8];
            }
#pragma unroll
            for (int nf = 0; nf < 4; nf++) {
                int cb = warp_n * 32 + nf * 8 + g_r;
                bf[0][nf][0] = Bs[0][ks * 8 + g_c    ][cb];
                bf[0][nf][1] = Bs[0][ks * 8 + g_c + 4][cb];
                bf[1][nf][0] = Bs[1][ks * 8 + g_c    ][cb];
                bf[1][nf][1] = Bs[1][ks * 8 + g_c + 4][cb];
            }
#pragma unroll
            for (int mf = 0; mf < 2; mf++)
#pragma unroll
                for (int nf = 0; nf < 4; nf++) {
                    mma_tf32(accg[mf][nf], af[mf], bf[0][nf]);
                    mma_tf32(accu[mf][nf], af[mf], bf[1][nf]);
                }
        }
    }

    float* hb = d_hbuf + (sh ? (size_t)NEXP * NTOK * MR : (size_t)job * NTOK * MR);
#pragma unroll
    for (int mf = 0; mf < 2; mf++)
#pragma unroll
        for (int nf = 0; nf < 4; nf++)
#pragma unroll
            for (int i = 0; i < 4; i++) {
                int r = warp_m * 32 + mf * 16 + g_r + ((i >= 2) ? 8 : 0);
                int c = warp_n * 32 + nf * 8 + g_c * 2 + (i & 1);
                int gr = row0 + r;
                if (gr < cnt) {
                    float g = accg[mf][nf][i], u = accu[mf][nf][i];
                    float hval = g / (1.f + __expf(-g)) * u;   // silu(g)*u
                    hb[(size_t)gr * Mdim + col0 + c] = hval;
                }
            }
}

// -------- kernel 3: down-proj + weighted scatter-add into y --------
__global__ __launch_bounds__(256) void down_kernel(
    const float* __restrict__ Wd, const float* __restrict__ sWd,
    float* __restrict__ y)
{
    const int  job = blockIdx.z;
    const bool sh  = (job == NEXP);
    const int  Kdim = sh ? MSH : MR;
    const int  cnt  = sh ? NTOK : d_counts[job];
    const int  row0 = blockIdx.y * BM;
    const int  col0 = blockIdx.x * BN;   // over H
    if (row0 >= cnt) return;

    const float* Bp = sh ? sWd : Wd + (size_t)job * MR * H;
    const float* Ap = d_hbuf + (sh ? (size_t)NEXP * NTOK * MR : (size_t)job * NTOK * MR);

    __shared__ uint32_t As[BK][BM + 4];
    __shared__ uint32_t Bs[BK][BN + 4];

    const int tid = threadIdx.x;
    const int lane = tid & 31;
    const int wid = tid >> 5;
    const int warp_m = wid & 3;
    const int warp_n = wid >> 2;
    const int g_r = lane >> 2;
    const int g_c = lane & 3;

    const float* aptr[4]; int arow[4], akq[4];
#pragma unroll
    for (int i = 0; i < 4; i++) {
        int idx = tid + i * 256;
        int r = idx >> 3, kq = idx & 7;
        arow[i] = r; akq[i] = kq;
        aptr[i] = Ap + (size_t)(row0 + r) * Kdim + kq * 4;   // rows are contiguous slots
    }
    const float* bptr[2]; int bkr[2], bnq[2];
#pragma unroll
    for (int i = 0; i < 2; i++) {
        int idx = tid + i * 256;
        int kr = idx >> 4, nq = idx & 15;
        bkr[i] = kr; bnq[i] = nq;
        bptr[i] = Bp + (size_t)kr * H + col0 + nq * 4;
    }

    float acc[2][4][4];
#pragma unroll
    for (int a = 0; a < 2; a++)
#pragma unroll
        for (int b = 0; b < 4; b++)
#pragma unroll
            for (int c = 0; c < 4; c++) acc[a][b][c] = 0.f;

    // prefetch iteration 0
    float4 av[4], bv[2];
#pragma unroll
    for (int i = 0; i < 4; i++) { av[i] = *reinterpret_cast<const float4*>(aptr[i]); aptr[i] += BK; }
#pragma unroll
    for (int i = 0; i < 2; i++) { bv[i] = *reinterpret_cast<const float4*>(bptr[i]); bptr[i] += (size_t)BK * H; }

    const int KT = Kdim / BK;
    for (int kt = 0; kt < KT; kt++) {
        __syncthreads();
#pragma unroll
        for (int i = 0; i < 4; i++) {
            As[akq[i] * 4 + 0][arow[i]] = f2tf(av[i].x);
            As[akq[i] * 4 + 1][arow[i]] = f2tf(av[i].y);
            As[akq[i] * 4 + 2][arow[i]] = f2tf(av[i].z);
            As[akq[i] * 4 + 3][arow[i]] = f2tf(av[i].w);
        }
#pragma unroll
        for (int i = 0; i < 2; i++) {
            Bs[bkr[i]][bnq[i] * 4 + 0] = f2tf(bv[i].x);
            Bs[bkr[i]][bnq[i] * 4 + 1] = f2tf(bv[i].y);
            Bs[bkr[i]][bnq[i] * 4 + 2] = f2tf(bv[i].z);
            Bs[bkr[i]][bnq[i] * 4 + 3] = f2tf(bv[i].w);
        }
        __syncthreads();

        if (kt + 1 < KT) {
#pragma unroll
            for (int i = 0; i < 4; i++) { av[i] = *reinterpret_cast<const float4*>(aptr[i]); aptr[i] += BK; }
#pragma unroll
            for (int i = 0; i < 2; i++) { bv[i] = *reinterpret_cast<const float4*>(bptr[i]); bptr[i] += (size_t)BK * H; }
        }

#pragma unroll
        for (int ks = 0; ks < BK / 8; ks++) {
            uint32_t af[2][4], bf[4][2];
#pragma unroll
            for (int mf = 0; mf < 2; mf++) {
                int rb = warp_m * 32 + mf * 16 + g_r;
                af[mf][0] = As[ks * 8 + g_c    ][rb    ];
                af[mf][1] = As[ks * 8 + g_c    ][rb + 8];
                af[mf][2] = As[ks * 8 + g_c + 4][rb    ];
                af[mf][3] = As[ks * 8 + g_c + 4][rb + 8];
            }
#pragma unroll
            for (int nf = 0; nf < 4; nf++) {
                int cb = warp_n * 32 + nf * 8 + g_r;
                bf[nf][0] = Bs[ks * 8 + g_c    ][cb];
                bf[nf][1] = Bs[ks * 8 + g_c + 4][cb];
            }
#pragma unroll
            for (int mf = 0; mf < 2; mf++)
#pragma unroll
                for (int nf = 0; nf < 4; nf++)
                    mma_tf32(acc[mf][nf], af[mf], bf[nf]);
        }
    }

    // epilogue: weighted scatter-add
#pragma unroll
    for (int mf = 0; mf < 2; mf++)
#pragma unroll
        for (int nf = 0; nf < 4; nf++)
#pragma unroll
            for (int i = 0; i < 4; i++) {
                int r = warp_m * 32 + mf * 16 + g_r + ((i >= 2) ? 8 : 0);
                int c = warp_n * 32 + nf * 8 + g_c * 2 + (i & 1);
                int gr = row0 + r;
                if (gr < cnt) {
                    int   tok = sh ? gr : d_tok[job * NTOK + gr];
                    float w   = sh ? 1.f : d_wt[job * NTOK + gr];
                    atomicAdd(&y[(size_t)tok * H + col0 + c], w * acc[mf][nf][i]);
                }
            }
}

extern "C" void kernel_launch(void* const* d_in, const int* in_sizes, int n_in,
                              void* d_out, int out_size) {
    const float* x   = (const float*)d_in[0];
    const float* gw  = (const float*)d_in[1];
    const float* Wg  = (const float*)d_in[2];
    const float* Wu  = (const float*)d_in[3];
    const float* Wd  = (const float*)d_in[4];
    const float* sWg = (const float*)d_in[5];
    const float* sWu = (const float*)d_in[6];
    const float* sWd = (const float*)d_in[7];
    float* y = (float*)d_out;

    zero_kernel<<<(NTOK * H / 4) / 256, 256>>>(y);
    gate_kernel<<<NTOK / 8, 256>>>(x, gw);

    dim3 g1(MSH / BN, NTOK / BM, NJOBS);   // 16 x 16 x 9
    gateup_kernel<<<g1, 256>>>(x, Wg, Wu, sWg, sWu);

    dim3 g2(H / BN, NTOK / BM, NJOBS);     // 32 x 16 x 9
    down_kernel<<<g2, 256>>>(Wd, sWd, y);
}

// round 5
// speedup vs baseline: 1.4468x; 1.4468x over previous
#include <cuda_runtime.h>
#include <cuda_bf16.h>
#include <cstdint>

// Problem constants
#define H     2048
#define NTOK  2048      // B*S
#define MR    512       // routed intermediate
#define MSH   1024      // shared intermediate
#define NEXP  8
#define NJOBS 9         // 8 routed experts + 1 shared "expert"

// GEMM tiling
#define BM 128
#define BN 64
#define BK 32
#define ASTRIDE 36      // (BK+4) words: conflict-free A fragment loads
#define BSTRIDE 72      // (BN+8) words: conflict-free B fragment loads

// -------- scratch (no mallocs allowed) --------
__device__ int   d_counts[NEXP];
__device__ int   d_tok[NEXP * NTOK];
__device__ float d_wt [NEXP * NTOK];

// one big scratch: tf32-rounded copies of x + all weights, plus h buffer
#define OFF_XC   ((size_t)0)                              // NTOK*H
#define OFF_WG   (OFF_XC  + (size_t)NTOK * H)             // NEXP*H*MR
#define OFF_WU   (OFF_WG  + (size_t)NEXP * H * MR)
#define OFF_WD   (OFF_WU  + (size_t)NEXP * H * MR)        // NEXP*MR*H
#define OFF_SWG  (OFF_WD  + (size_t)NEXP * MR * H)        // H*MSH
#define OFF_SWU  (OFF_SWG + (size_t)H * MSH)
#define OFF_SWD  (OFF_SWU + (size_t)H * MSH)              // MSH*H
#define OFF_HB   (OFF_SWD + (size_t)MSH * H)              // routed h: NEXP*NTOK*MR
#define OFF_HBS  (OFF_HB  + (size_t)NEXP * NTOK * MR)     // shared h: NTOK*MSH
#define SCRATCH_TOTAL (OFF_HBS + (size_t)NTOK * MSH)

__device__ float d_scratch[SCRATCH_TOTAL];

// -------- helpers --------
__device__ __forceinline__ uint32_t f2tf(float x) {
    uint32_t r;
    asm("cvt.rna.tf32.f32 %0, %1;" : "=r"(r) : "f"(x));
    return r;
}

__device__ __forceinline__ void cp16(void* smem_dst, const void* gmem_src) {
    uint32_t s = (uint32_t)__cvta_generic_to_shared(smem_dst);
    asm volatile("cp.async.cg.shared.global [%0], [%1], 16;\n" :: "r"(s), "l"(gmem_src));
}
__device__ __forceinline__ void cp_commit() {
    asm volatile("cp.async.commit_group;\n");
}
__device__ __forceinline__ void cp_wait0() {
    asm volatile("cp.async.wait_group 0;\n");
}

__device__ __forceinline__ void mma_tf32(float* c, const uint32_t* a, const uint32_t* b) {
    asm volatile(
        "mma.sync.aligned.m16n8k8.row.col.f32.tf32.tf32.f32 "
        "{%0,%1,%2,%3}, {%4,%5,%6,%7}, {%8,%9}, {%0,%1,%2,%3};\n"
        : "+f"(c[0]), "+f"(c[1]), "+f"(c[2]), "+f"(c[3])
        : "r"(a[0]), "r"(a[1]), "r"(a[2]), "r"(a[3]),
          "r"(b[0]), "r"(b[1]));
}

// -------- kernel A: tf32-round a tensor (float4 granularity) --------
__global__ void cvt_kernel(const float4* __restrict__ src, float4* __restrict__ dst, int n4) {
    int i = blockIdx.x * blockDim.x + threadIdx.x;
    if (i < n4) {
        float4 v = src[i];
        float4 o;
        o.x = __uint_as_float(f2tf(v.x));
        o.y = __uint_as_float(f2tf(v.y));
        o.z = __uint_as_float(f2tf(v.z));
        o.w = __uint_as_float(f2tf(v.w));
        dst[i] = o;
    }
}

// -------- kernel 0: reset routing counts --------
__global__ void reset_kernel() {
    if (threadIdx.x < NEXP) d_counts[threadIdx.x] = 0;
}

// -------- kernel 1: gate logits + top2 + softmax + route lists --------
__global__ void gate_kernel(const float* __restrict__ x, const float* __restrict__ gw) {
    int warp = blockIdx.x * (blockDim.x >> 5) + (threadIdx.x >> 5);
    int lane = threadIdx.x & 31;
    if (warp >= NTOK) return;
    int t = warp;
    const float4* x4 = reinterpret_cast<const float4*>(x + (size_t)t * H);
    const float4* g4 = reinterpret_cast<const float4*>(gw);
    float acc[NEXP];
#pragma unroll
    for (int e = 0; e < NEXP; e++) acc[e] = 0.f;
    for (int i = lane; i < H / 4; i += 32) {
        float4 xv = x4[i];
#pragma unroll
        for (int e = 0; e < NEXP; e++) {
            float4 gv = g4[e * (H / 4) + i];
            acc[e] += xv.x * gv.x + xv.y * gv.y + xv.z * gv.z + xv.w * gv.w;
        }
    }
#pragma unroll
    for (int e = 0; e < NEXP; e++)
#pragma unroll
        for (int o = 16; o; o >>= 1) acc[e] += __shfl_xor_sync(0xffffffffu, acc[e], o);
    if (lane == 0) {
        int i0 = 0; float v0 = acc[0];
#pragma unroll
        for (int e = 1; e < NEXP; e++) if (acc[e] > v0) { v0 = acc[e]; i0 = e; }
        int i1 = -1; float v1 = -1e30f;
#pragma unroll
        for (int e = 0; e < NEXP; e++) if (e != i0 && acc[e] > v1) { v1 = acc[e]; i1 = e; }
        float e1 = __expf(v1 - v0);
        float s  = 1.f + e1;
        float w0 = 1.f / s, w1 = e1 / s;
        int p0 = atomicAdd(&d_counts[i0], 1);
        d_tok[i0 * NTOK + p0] = t; d_wt[i0 * NTOK + p0] = w0;
        int p1 = atomicAdd(&d_counts[i1], 1);
        d_tok[i1 * NTOK + p1] = t; d_wt[i1 * NTOK + p1] = w1;
    }
}

// -------- kernel 2: fused gate+up dual-GEMM + SiLU*u epilogue --------
// cp.async double-buffered; all inputs pre-rounded to tf32.
__global__ __launch_bounds__(256) void gateup_kernel() {
    const int  job = blockIdx.z;
    const bool sh  = (job == NEXP);
    const int  Mdim = sh ? MSH : MR;
    const int  cnt  = sh ? NTOK : d_counts[job];
    const int  row0 = blockIdx.y * BM;
    const int  col0 = blockIdx.x * BN;
    if (row0 >= cnt || col0 >= Mdim) return;

    const float* xc = d_scratch + OFF_XC;
    const float* Bg = sh ? d_scratch + OFF_SWG : d_scratch + OFF_WG + (size_t)job * H * MR;
    const float* Bu = sh ? d_scratch + OFF_SWU : d_scratch + OFF_WU + (size_t)job * H * MR;

    extern __shared__ uint32_t smp[];
    uint32_t* As  = smp;                        // [2][BM][ASTRIDE]
    uint32_t* Bgs = smp + 2 * BM * ASTRIDE;     // [2][BK][BSTRIDE]
    uint32_t* Bus = Bgs + 2 * BK * BSTRIDE;     // [2][BK][BSTRIDE]

    const int tid = threadIdx.x;
    const int lane = tid & 31;
    const int wid = tid >> 5;
    const int warp_m = wid & 3;
    const int warp_n = wid >> 2;
    const int g_r = lane >> 2;
    const int g_c = lane & 3;

    // A: 4 16B-chunks/thread. chunk -> (m, kquad)
    const float* asrc[4]; int adst[4];
#pragma unroll
    for (int i = 0; i < 4; i++) {
        int idx = tid + i * 256;
        int m = idx >> 3, kq = idx & 7;
        int gl = row0 + m; if (gl >= cnt) gl = cnt - 1;
        int tok = sh ? gl : d_tok[job * NTOK + gl];
        asrc[i] = xc + (size_t)tok * H + kq * 4;
        adst[i] = m * ASTRIDE + kq * 4;
    }
    // B: 2 chunks/thread per matrix. chunk -> (k, nquad)
    const float* bsrcg[2]; const float* bsrcu[2]; int bdst[2];
#pragma unroll
    for (int i = 0; i < 2; i++) {
        int idx = tid + i * 256;
        int kr = idx >> 4, nq = idx & 15;
        bsrcg[i] = Bg + (size_t)kr * Mdim + col0 + nq * 4;
        bsrcu[i] = Bu + (size_t)kr * Mdim + col0 + nq * 4;
        bdst[i]  = kr * BSTRIDE + nq * 4;
    }

    float accg[2][4][4], accu[2][4][4];
#pragma unroll
    for (int a = 0; a < 2; a++)
#pragma unroll
        for (int b = 0; b < 4; b++)
#pragma unroll
            for (int c = 0; c < 4; c++) { accg[a][b][c] = 0.f; accu[a][b][c] = 0.f; }

    const int KT = H / BK;

    // prologue: stage 0
#pragma unroll
    for (int i = 0; i < 4; i++) cp16(As + adst[i], asrc[i]);
#pragma unroll
    for (int i = 0; i < 2; i++) {
        cp16(Bgs + bdst[i], bsrcg[i]);
        cp16(Bus + bdst[i], bsrcu[i]);
    }
    cp_commit();

    for (int kt = 0; kt < KT; kt++) {
        cp_wait0();
        __syncthreads();   // stage (kt&1) visible; prev MMA done -> other buffer free

        if (kt + 1 < KT) {
            int nb = (kt + 1) & 1;
            size_t ka = (size_t)(kt + 1) * BK;
            size_t kb = (size_t)(kt + 1) * BK * Mdim;
#pragma unroll
            for (int i = 0; i < 4; i++) cp16(As + nb * BM * ASTRIDE + adst[i], asrc[i] + ka);
#pragma unroll
            for (int i = 0; i < 2; i++) {
                cp16(Bgs + nb * BK * BSTRIDE + bdst[i], bsrcg[i] + kb);
                cp16(Bus + nb * BK * BSTRIDE + bdst[i], bsrcu[i] + kb);
            }
            cp_commit();
        }

        const uint32_t* Ac  = As  + (kt & 1) * BM * ASTRIDE;
        const uint32_t* Bgc = Bgs + (kt & 1) * BK * BSTRIDE;
        const uint32_t* Buc = Bus + (kt & 1) * BK * BSTRIDE;

#pragma unroll
        for (int ks = 0; ks < BK / 8; ks++) {
            uint32_t af[2][4], bg[4][2], bu[4][2];
#pragma unroll
            for (int mf = 0; mf < 2; mf++) {
                int rb = warp_m * 32 + mf * 16 + g_r;
                af[mf][0] = Ac[(size_t)rb * ASTRIDE       + ks * 8 + g_c];
                af[mf][1] = Ac[(size_t)(rb + 8) * ASTRIDE + ks * 8 + g_c];
                af[mf][2] = Ac[(size_t)rb * ASTRIDE       + ks * 8 + g_c + 4];
                af[mf][3] = Ac[(size_t)(rb + 8) * ASTRIDE + ks * 8 + g_c + 4];
            }
#pragma unroll
            for (int nf = 0; nf < 4; nf++) {
                int cb = warp_n * 32 + nf * 8 + g_r;
                bg[nf][0] = Bgc[(ks * 8 + g_c) * BSTRIDE     + cb];
                bg[nf][1] = Bgc[(ks * 8 + g_c + 4) * BSTRIDE + cb];
                bu[nf][0] = Buc[(ks * 8 + g_c) * BSTRIDE     + cb];
                bu[nf][1] = Buc[(ks * 8 + g_c + 4) * BSTRIDE + cb];
            }
#pragma unroll
            for (int mf = 0; mf < 2; mf++)
#pragma unroll
                for (int nf = 0; nf < 4; nf++) {
                    mma_tf32(accg[mf][nf], af[mf], bg[nf]);
                    mma_tf32(accu[mf][nf], af[mf], bu[nf]);
                }
        }
    }

    float* hb = d_scratch + (sh ? OFF_HBS : OFF_HB + (size_t)job * NTOK * MR);
#pragma unroll
    for (int mf = 0; mf < 2; mf++)
#pragma unroll
        for (int nf = 0; nf < 4; nf++)
#pragma unroll
            for (int i = 0; i < 4; i++) {
                int r = warp_m * 32 + mf * 16 + g_r + ((i >= 2) ? 8 : 0);
                int c = warp_n * 32 + nf * 8 + g_c * 2 + (i & 1);
                int gr = row0 + r;
                if (gr < cnt) {
                    float g = accg[mf][nf][i], u = accu[mf][nf][i];
                    float hval = g / (1.f + __expf(-g)) * u;   // silu(g)*u
                    // store pre-rounded so down kernels need no cvt
                    hb[(size_t)gr * Mdim + col0 + c] = __uint_as_float(f2tf(hval));
                }
            }
}

// -------- kernel 3: down-proj --------
// SHARED=true : dense shared expert, writes y directly (covers every element
//               exactly once -> no zeroing pass, no atomics)
// SHARED=false: routed experts (blockIdx.z = expert), weighted atomicAdd on top
template <bool SHARED>
__global__ __launch_bounds__(256) void down_kernel(float* __restrict__ y) {
    const int  job  = SHARED ? 0 : blockIdx.z;
    const int  Kdim = SHARED ? MSH : MR;
    const int  cnt  = SHARED ? NTOK : d_counts[job];
    const int  row0 = blockIdx.y * BM;
    const int  col0 = blockIdx.x * BN;   // over H
    if (row0 >= cnt) return;

    const float* Bp = SHARED ? d_scratch + OFF_SWD : d_scratch + OFF_WD + (size_t)job * MR * H;
    const float* Ap = SHARED ? d_scratch + OFF_HBS : d_scratch + OFF_HB + (size_t)job * NTOK * MR;

    extern __shared__ uint32_t smp[];
    uint32_t* As = smp;                    // [2][BM][ASTRIDE]
    uint32_t* Bs = smp + 2 * BM * ASTRIDE; // [2][BK][BSTRIDE]

    const int tid = threadIdx.x;
    const int lane = tid & 31;
    const int wid = tid >> 5;
    const int warp_m = wid & 3;
    const int warp_n = wid >> 2;
    const int g_r = lane >> 2;
    const int g_c = lane & 3;

    const float* asrc[4]; int adst[4];
#pragma unroll
    for (int i = 0; i < 4; i++) {
        int idx = tid + i * 256;
        int m = idx >> 3, kq = idx & 7;
        asrc[i] = Ap + (size_t)(row0 + m) * Kdim + kq * 4;
        adst[i] = m * ASTRIDE + kq * 4;
    }
    const float* bsrc[2]; int bdst[2];
#pragma unroll
    for (int i = 0; i < 2; i++) {
        int idx = tid + i * 256;
        int kr = idx >> 4, nq = idx & 15;
        bsrc[i] = Bp + (size_t)kr * H + col0 + nq * 4;
        bdst[i] = kr * BSTRIDE + nq * 4;
    }

    float acc[2][4][4];
#pragma unroll
    for (int a = 0; a < 2; a++)
#pragma unroll
        for (int b = 0; b < 4; b++)
#pragma unroll
            for (int c = 0; c < 4; c++) acc[a][b][c] = 0.f;

    const int KT = Kdim / BK;

#pragma unroll
    for (int i = 0; i < 4; i++) cp16(As + adst[i], asrc[i]);
#pragma unroll
    for (int i = 0; i < 2; i++) cp16(Bs + bdst[i], bsrc[i]);
    cp_commit();

    for (int kt = 0; kt < KT; kt++) {
        cp_wait0();
        __syncthreads();

        if (kt + 1 < KT) {
            int nb = (kt + 1) & 1;
            size_t ka = (size_t)(kt + 1) * BK;
            size_t kb = (size_t)(kt + 1) * BK * H;
#pragma unroll
            for (int i = 0; i < 4; i++) cp16(As + nb * BM * ASTRIDE + adst[i], asrc[i] + ka);
#pragma unroll
            for (int i = 0; i < 2; i++) cp16(Bs + nb * BK * BSTRIDE + bdst[i], bsrc[i] + kb);
            cp_commit();
        }

        const uint32_t* Ac = As + (kt & 1) * BM * ASTRIDE;
        const uint32_t* Bc = Bs + (kt & 1) * BK * BSTRIDE;

#pragma unroll
        for (int ks = 0; ks < BK / 8; ks++) {
            uint32_t af[2][4], bf[4][2];
#pragma unroll
            for (int mf = 0; mf < 2; mf++) {
                int rb = warp_m * 32 + mf * 16 + g_r;
                af[mf][0] = Ac[(size_t)rb * ASTRIDE       + ks * 8 + g_c];
                af[mf][1] = Ac[(size_t)(rb + 8) * ASTRIDE + ks * 8 + g_c];
                af[mf][2] = Ac[(size_t)rb * ASTRIDE       + ks * 8 + g_c + 4];
                af[mf][3] = Ac[(size_t)(rb + 8) * ASTRIDE + ks * 8 + g_c + 4];
            }
#pragma unroll
            for (int nf = 0; nf < 4; nf++) {
                int cb = warp_n * 32 + nf * 8 + g_r;
                bf[nf][0] = Bc[(ks * 8 + g_c) * BSTRIDE     + cb];
                bf[nf][1] = Bc[(ks * 8 + g_c + 4) * BSTRIDE + cb];
            }
#pragma unroll
            for (int mf = 0; mf < 2; mf++)
#pragma unroll
                for (int nf = 0; nf < 4; nf++)
                    mma_tf32(acc[mf][nf], af[mf], bf[nf]);
        }
    }

    // epilogue
#pragma unroll
    for (int mf = 0; mf < 2; mf++)
#pragma unroll
        for (int nf = 0; nf < 4; nf++)
#pragma unroll
            for (int i = 0; i < 4; i++) {
                int r = warp_m * 32 + mf * 16 + g_r + ((i >= 2) ? 8 : 0);
                int c = warp_n * 32 + nf * 8 + g_c * 2 + (i & 1);
                int gr = row0 + r;
                if (gr < cnt) {
                    if (SHARED) {
                        y[(size_t)gr * H + col0 + c] = acc[mf][nf][i];
                    } else {
                        int   tok = d_tok[job * NTOK + gr];
                        float w   = d_wt[job * NTOK + gr];
                        atomicAdd(&y[(size_t)tok * H + col0 + c], w * acc[mf][nf][i]);
                    }
                }
            }
}

extern "C" void kernel_launch(void* const* d_in, const int* in_sizes, int n_in,
                              void* d_out, int out_size) {
    const float* x   = (const float*)d_in[0];
    const float* gw  = (const float*)d_in[1];
    const float* Wg  = (const float*)d_in[2];
    const float* Wu  = (const float*)d_in[3];
    const float* Wd  = (const float*)d_in[4];
    const float* sWg = (const float*)d_in[5];
    const float* sWu = (const float*)d_in[6];
    const float* sWd = (const float*)d_in[7];
    float* y = (float*)d_out;

    float* sp = nullptr;
    cudaGetSymbolAddress((void**)&sp, d_scratch);

    // tf32-round all GEMM inputs once (bit-exact with in-loop cvt.rna since
    // mma.tf32 hardware-truncates the low mantissa bits of fp32 operands)
    struct { const float* src; size_t off; size_t n; } cv[7] = {
        { x,   OFF_XC,  (size_t)NTOK * H      },
        { Wg,  OFF_WG,  (size_t)NEXP * H * MR },
        { Wu,  OFF_WU,  (size_t)NEXP * H * MR },
        { Wd,  OFF_WD,  (size_t)NEXP * MR * H },
        { sWg, OFF_SWG, (size_t)H * MSH       },
        { sWu, OFF_SWU, (size_t)H * MSH       },
        { sWd, OFF_SWD, (size_t)MSH * H       },
    };
    for (int i = 0; i < 7; i++) {
        int n4 = (int)(cv[i].n / 4);
        cvt_kernel<<<(n4 + 255) / 256, 256>>>(
            (const float4*)cv[i].src, (float4*)(sp + cv[i].off), n4);
    }

    reset_kernel<<<1, 32>>>();
    gate_kernel<<<NTOK / 8, 256>>>(x, gw);

    const int smem_gu = (2 * BM * ASTRIDE + 4 * BK * BSTRIDE) * 4;   // 73728
    const int smem_dn = (2 * BM * ASTRIDE + 2 * BK * BSTRIDE) * 4;   // 55296
    cudaFuncSetAttribute(gateup_kernel,      cudaFuncAttributeMaxDynamicSharedMemorySize, smem_gu);
    cudaFuncSetAttribute(down_kernel<true>,  cudaFuncAttributeMaxDynamicSharedMemorySize, smem_dn);
    cudaFuncSetAttribute(down_kernel<false>, cudaFuncAttributeMaxDynamicSharedMemorySize, smem_dn);

    dim3 g1(MSH / BN, NTOK / BM, NJOBS);   // 16 x 16 x 9
    gateup_kernel<<<g1, 256, smem_gu>>>();

    // shared expert writes y fully (plain stores) ...
    dim3 g2s(H / BN, NTOK / BM, 1);        // 32 x 16
    down_kernel<true><<<g2s, 256, smem_dn>>>(y);
    // ... then routed experts accumulate on top (stream order = dependency)
    dim3 g2r(H / BN, NTOK / BM, NEXP);     // 32 x 16 x 8
    down_kernel<false><<<g2r, 256, smem_dn>>>(y);
}

// round 6
// speedup vs baseline: 1.5461x; 1.0686x over previous
#include <cuda_runtime.h>
#include <cuda_bf16.h>
#include <cstdint>

// Problem constants
#define H     2048
#define NTOK  2048      // B*S
#define MR    512       // routed intermediate
#define MSH   1024      // shared intermediate
#define NEXP  8
#define NJOBS 9         // 8 routed experts + 1 shared "expert"

// gateup GEMM tiling
#define BM 128
#define BN 64
#define BK 32
#define ASTRIDE 36      // (BK+4) words: conflict-free A fragment loads
#define BSTRIDE 72      // (BN+8) words: conflict-free B fragment loads

// down GEMM tiling (wider N)
#define DBN 128
#define DBSTRIDE 136    // (DBN+8) words, 136 mod 32 = 8 -> conflict-free

// -------- scratch (no mallocs allowed) --------
__device__ int   d_counts[NEXP];
__device__ int   d_tok[NEXP * NTOK];
__device__ float d_wt [NEXP * NTOK];

// one big scratch: tf32-rounded copies of x + all weights (CONTIGUOUS, in
// cvt_all segment order), plus h buffers
#define OFF_XC   ((size_t)0)                              // NTOK*H
#define OFF_WG   (OFF_XC  + (size_t)NTOK * H)             // NEXP*H*MR
#define OFF_WU   (OFF_WG  + (size_t)NEXP * H * MR)
#define OFF_WD   (OFF_WU  + (size_t)NEXP * H * MR)        // NEXP*MR*H
#define OFF_SWG  (OFF_WD  + (size_t)NEXP * MR * H)        // H*MSH
#define OFF_SWU  (OFF_SWG + (size_t)H * MSH)
#define OFF_SWD  (OFF_SWU + (size_t)H * MSH)              // MSH*H
#define OFF_HB   (OFF_SWD + (size_t)MSH * H)              // routed h: NEXP*NTOK*MR
#define OFF_HBS  (OFF_HB  + (size_t)NEXP * NTOK * MR)     // shared h: NTOK*MSH
#define SCRATCH_TOTAL (OFF_HBS + (size_t)NTOK * MSH)

__device__ float d_scratch[SCRATCH_TOTAL];

// cumulative float4 boundaries of the 7 convert segments
#define C0 ((size_t)0)
#define C1 (OFF_WG  / 4)
#define C2 (OFF_WU  / 4)
#define C3 (OFF_WD  / 4)
#define C4 (OFF_SWG / 4)
#define C5 (OFF_SWU / 4)
#define C6 (OFF_SWD / 4)
#define C7 (OFF_HB  / 4)

// -------- helpers --------
__device__ __forceinline__ uint32_t f2tf(float x) {
    uint32_t r;
    asm("cvt.rna.tf32.f32 %0, %1;" : "=r"(r) : "f"(x));
    return r;
}

__device__ __forceinline__ void cp16(void* smem_dst, const void* gmem_src) {
    uint32_t s = (uint32_t)__cvta_generic_to_shared(smem_dst);
    asm volatile("cp.async.cg.shared.global [%0], [%1], 16;\n" :: "r"(s), "l"(gmem_src));
}
__device__ __forceinline__ void cp_commit() {
    asm volatile("cp.async.commit_group;\n");
}
__device__ __forceinline__ void cp_wait0() {
    asm volatile("cp.async.wait_group 0;\n");
}

__device__ __forceinline__ void mma_tf32(float* c, const uint32_t* a, const uint32_t* b) {
    asm volatile(
        "mma.sync.aligned.m16n8k8.row.col.f32.tf32.tf32.f32 "
        "{%0,%1,%2,%3}, {%4,%5,%6,%7}, {%8,%9}, {%0,%1,%2,%3};\n"
        : "+f"(c[0]), "+f"(c[1]), "+f"(c[2]), "+f"(c[3])
        : "r"(a[0]), "r"(a[1]), "r"(a[2]), "r"(a[3]),
          "r"(b[0]), "r"(b[1]));
}

// -------- kernel A: tf32-round ALL inputs in one launch --------
// scratch segments are laid out in source order, so dst index == global index.
__global__ void cvt_all_kernel(
    const float4* __restrict__ s0, const float4* __restrict__ s1,
    const float4* __restrict__ s2, const float4* __restrict__ s3,
    const float4* __restrict__ s4, const float4* __restrict__ s5,
    const float4* __restrict__ s6)
{
    float4* out = reinterpret_cast<float4*>(d_scratch);
    const size_t total = C7;
    size_t stride = (size_t)gridDim.x * blockDim.x;
    for (size_t i = (size_t)blockIdx.x * blockDim.x + threadIdx.x; i < total; i += stride) {
        const float4* src; size_t off;
        if      (i < C1) { src = s0; off = i;      }
        else if (i < C2) { src = s1; off = i - C1; }
        else if (i < C3) { src = s2; off = i - C2; }
        else if (i < C4) { src = s3; off = i - C3; }
        else if (i < C5) { src = s4; off = i - C4; }
        else if (i < C6) { src = s5; off = i - C5; }
        else             { src = s6; off = i - C6; }
        float4 v = src[off];
        float4 o;
        o.x = __uint_as_float(f2tf(v.x));
        o.y = __uint_as_float(f2tf(v.y));
        o.z = __uint_as_float(f2tf(v.z));
        o.w = __uint_as_float(f2tf(v.w));
        out[i] = o;
    }
}

// -------- kernel 0: reset routing counts --------
__global__ void reset_kernel() {
    if (threadIdx.x < NEXP) d_counts[threadIdx.x] = 0;
}

// -------- kernel 1: gate logits + top2 + softmax + route lists --------
__global__ void gate_kernel(const float* __restrict__ x, const float* __restrict__ gw) {
    int warp = blockIdx.x * (blockDim.x >> 5) + (threadIdx.x >> 5);
    int lane = threadIdx.x & 31;
    if (warp >= NTOK) return;
    int t = warp;
    const float4* x4 = reinterpret_cast<const float4*>(x + (size_t)t * H);
    const float4* g4 = reinterpret_cast<const float4*>(gw);
    float acc[NEXP];
#pragma unroll
    for (int e = 0; e < NEXP; e++) acc[e] = 0.f;
    for (int i = lane; i < H / 4; i += 32) {
        float4 xv = x4[i];
#pragma unroll
        for (int e = 0; e < NEXP; e++) {
            float4 gv = g4[e * (H / 4) + i];
            acc[e] += xv.x * gv.x + xv.y * gv.y + xv.z * gv.z + xv.w * gv.w;
        }
    }
#pragma unroll
    for (int e = 0; e < NEXP; e++)
#pragma unroll
        for (int o = 16; o; o >>= 1) acc[e] += __shfl_xor_sync(0xffffffffu, acc[e], o);
    if (lane == 0) {
        int i0 = 0; float v0 = acc[0];
#pragma unroll
        for (int e = 1; e < NEXP; e++) if (acc[e] > v0) { v0 = acc[e]; i0 = e; }
        int i1 = -1; float v1 = -1e30f;
#pragma unroll
        for (int e = 0; e < NEXP; e++) if (e != i0 && acc[e] > v1) { v1 = acc[e]; i1 = e; }
        float e1 = __expf(v1 - v0);
        float s  = 1.f + e1;
        float w0 = 1.f / s, w1 = e1 / s;
        int p0 = atomicAdd(&d_counts[i0], 1);
        d_tok[i0 * NTOK + p0] = t; d_wt[i0 * NTOK + p0] = w0;
        int p1 = atomicAdd(&d_counts[i1], 1);
        d_tok[i1 * NTOK + p1] = t; d_wt[i1 * NTOK + p1] = w1;
    }
}

// -------- kernel 2: fused gate+up dual-GEMM + SiLU*u epilogue --------
// cp.async double-buffered; all inputs pre-rounded to tf32. (unchanged, R5-validated)
__global__ __launch_bounds__(256) void gateup_kernel() {
    const int  job = blockIdx.z;
    const bool sh  = (job == NEXP);
    const int  Mdim = sh ? MSH : MR;
    const int  cnt  = sh ? NTOK : d_counts[job];
    const int  row0 = blockIdx.y * BM;
    const int  col0 = blockIdx.x * BN;
    if (row0 >= cnt || col0 >= Mdim) return;

    const float* xc = d_scratch + OFF_XC;
    const float* Bg = sh ? d_scratch + OFF_SWG : d_scratch + OFF_WG + (size_t)job * H * MR;
    const float* Bu = sh ? d_scratch + OFF_SWU : d_scratch + OFF_WU + (size_t)job * H * MR;

    extern __shared__ uint32_t smp[];
    uint32_t* As  = smp;                        // [2][BM][ASTRIDE]
    uint32_t* Bgs = smp + 2 * BM * ASTRIDE;     // [2][BK][BSTRIDE]
    uint32_t* Bus = Bgs + 2 * BK * BSTRIDE;     // [2][BK][BSTRIDE]

    const int tid = threadIdx.x;
    const int lane = tid & 31;
    const int wid = tid >> 5;
    const int warp_m = wid & 3;
    const int warp_n = wid >> 2;
    const int g_r = lane >> 2;
    const int g_c = lane & 3;

    const float* asrc[4]; int adst[4];
#pragma unroll
    for (int i = 0; i < 4; i++) {
        int idx = tid + i * 256;
        int m = idx >> 3, kq = idx & 7;
        int gl = row0 + m; if (gl >= cnt) gl = cnt - 1;
        int tok = sh ? gl : d_tok[job * NTOK + gl];
        asrc[i] = xc + (size_t)tok * H + kq * 4;
        adst[i] = m * ASTRIDE + kq * 4;
    }
    const float* bsrcg[2]; const float* bsrcu[2]; int bdst[2];
#pragma unroll
    for (int i = 0; i < 2; i++) {
        int idx = tid + i * 256;
        int kr = idx >> 4, nq = idx & 15;
        bsrcg[i] = Bg + (size_t)kr * Mdim + col0 + nq * 4;
        bsrcu[i] = Bu + (size_t)kr * Mdim + col0 + nq * 4;
        bdst[i]  = kr * BSTRIDE + nq * 4;
    }

    float accg[2][4][4], accu[2][4][4];
#pragma unroll
    for (int a = 0; a < 2; a++)
#pragma unroll
        for (int b = 0; b < 4; b++)
#pragma unroll
            for (int c = 0; c < 4; c++) { accg[a][b][c] = 0.f; accu[a][b][c] = 0.f; }

    const int KT = H / BK;

#pragma unroll
    for (int i = 0; i < 4; i++) cp16(As + adst[i], asrc[i]);
#pragma unroll
    for (int i = 0; i < 2; i++) {
        cp16(Bgs + bdst[i], bsrcg[i]);
        cp16(Bus + bdst[i], bsrcu[i]);
    }
    cp_commit();

    for (int kt = 0; kt < KT; kt++) {
        cp_wait0();
        __syncthreads();

        if (kt + 1 < KT) {
            int nb = (kt + 1) & 1;
            size_t ka = (size_t)(kt + 1) * BK;
            size_t kb = (size_t)(kt + 1) * BK * Mdim;
#pragma unroll
            for (int i = 0; i < 4; i++) cp16(As + nb * BM * ASTRIDE + adst[i], asrc[i] + ka);
#pragma unroll
            for (int i = 0; i < 2; i++) {
                cp16(Bgs + nb * BK * BSTRIDE + bdst[i], bsrcg[i] + kb);
                cp16(Bus + nb * BK * BSTRIDE + bdst[i], bsrcu[i] + kb);
            }
            cp_commit();
        }

        const uint32_t* Ac  = As  + (kt & 1) * BM * ASTRIDE;
        const uint32_t* Bgc = Bgs + (kt & 1) * BK * BSTRIDE;
        const uint32_t* Buc = Bus + (kt & 1) * BK * BSTRIDE;

#pragma unroll
        for (int ks = 0; ks < BK / 8; ks++) {
            uint32_t af[2][4], bg[4][2], bu[4][2];
#pragma unroll
            for (int mf = 0; mf < 2; mf++) {
                int rb = warp_m * 32 + mf * 16 + g_r;
                af[mf][0] = Ac[(size_t)rb * ASTRIDE       + ks * 8 + g_c];
                af[mf][1] = Ac[(size_t)(rb + 8) * ASTRIDE + ks * 8 + g_c];
                af[mf][2] = Ac[(size_t)rb * ASTRIDE       + ks * 8 + g_c + 4];
                af[mf][3] = Ac[(size_t)(rb + 8) * ASTRIDE + ks * 8 + g_c + 4];
            }
#pragma unroll
            for (int nf = 0; nf < 4; nf++) {
                int cb = warp_n * 32 + nf * 8 + g_r;
                bg[nf][0] = Bgc[(ks * 8 + g_c) * BSTRIDE     + cb];
                bg[nf][1] = Bgc[(ks * 8 + g_c + 4) * BSTRIDE + cb];
                bu[nf][0] = Buc[(ks * 8 + g_c) * BSTRIDE     + cb];
                bu[nf][1] = Buc[(ks * 8 + g_c + 4) * BSTRIDE + cb];
            }
#pragma unroll
            for (int mf = 0; mf < 2; mf++)
#pragma unroll
                for (int nf = 0; nf < 4; nf++) {
                    mma_tf32(accg[mf][nf], af[mf], bg[nf]);
                    mma_tf32(accu[mf][nf], af[mf], bu[nf]);
                }
        }
    }

    float* hb = d_scratch + (sh ? OFF_HBS : OFF_HB + (size_t)job * NTOK * MR);
#pragma unroll
    for (int mf = 0; mf < 2; mf++)
#pragma unroll
        for (int nf = 0; nf < 4; nf++)
#pragma unroll
            for (int i = 0; i < 4; i++) {
                int r = warp_m * 32 + mf * 16 + g_r + ((i >= 2) ? 8 : 0);
                int c = warp_n * 32 + nf * 8 + g_c * 2 + (i & 1);
                int gr = row0 + r;
                if (gr < cnt) {
                    float g = accg[mf][nf][i], u = accu[mf][nf][i];
                    float hval = g / (1.f + __expf(-g)) * u;   // silu(g)*u
                    hb[(size_t)gr * Mdim + col0 + c] = __uint_as_float(f2tf(hval));
                }
            }
}

// -------- kernel 3: down-proj, BM=128 x DBN=128 tiles --------
// SHARED=true : dense shared expert, writes y directly (no zero pass, no atomics)
// SHARED=false: routed experts (blockIdx.z = expert), weighted atomicAdd on top
template <bool SHARED>
__global__ __launch_bounds__(256, 2) void down_kernel(float* __restrict__ y) {
    const int  job  = SHARED ? 0 : blockIdx.z;
    const int  Kdim = SHARED ? MSH : MR;
    const int  cnt  = SHARED ? NTOK : d_counts[job];
    const int  row0 = blockIdx.y * BM;
    const int  col0 = blockIdx.x * DBN;   // over H
    if (row0 >= cnt) return;

    const char* Bp = (const char*)(SHARED ? d_scratch + OFF_SWD
                                          : d_scratch + OFF_WD + (size_t)job * MR * H);
    const char* Ap = (const char*)(SHARED ? d_scratch + OFF_HBS
                                          : d_scratch + OFF_HB + (size_t)job * NTOK * MR);

    extern __shared__ uint32_t smp[];
    uint32_t* As = smp;                    // [2][BM][ASTRIDE]
    uint32_t* Bs = smp + 2 * BM * ASTRIDE; // [2][BK][DBSTRIDE]

    const int tid = threadIdx.x;
    const int lane = tid & 31;
    const int wid = tid >> 5;
    const int warp_m = wid & 3;
    const int warp_n = wid >> 2;
    const int g_r = lane >> 2;
    const int g_c = lane & 3;

    // A: 4 chunks/thread (BM*BK*4B = 16KB/stage); 32-bit byte offsets
    uint32_t aoff[4]; int adst[4];
#pragma unroll
    for (int i = 0; i < 4; i++) {
        int idx = tid + i * 256;
        int m = idx >> 3, kq = idx & 7;
        aoff[i] = (uint32_t)(((row0 + m) * Kdim + kq * 4) * 4);
        adst[i] = m * ASTRIDE + kq * 4;
    }
    // B: 4 chunks/thread (BK*DBN*4B = 16KB/stage)
    uint32_t boff[4]; int bdst[4];
#pragma unroll
    for (int i = 0; i < 4; i++) {
        int idx = tid + i * 256;
        int kr = idx >> 5, nq = idx & 31;
        boff[i] = (uint32_t)((kr * H + col0 + nq * 4) * 4);
        bdst[i] = kr * DBSTRIDE + nq * 4;
    }

    float acc[2][8][4];
#pragma unroll
    for (int a = 0; a < 2; a++)
#pragma unroll
        for (int b = 0; b < 8; b++)
#pragma unroll
            for (int c = 0; c < 4; c++) acc[a][b][c] = 0.f;

    const int KT = Kdim / BK;

#pragma unroll
    for (int i = 0; i < 4; i++) cp16(As + adst[i], Ap + aoff[i]);
#pragma unroll
    for (int i = 0; i < 4; i++) cp16(Bs + bdst[i], Bp + boff[i]);
    cp_commit();

    for (int kt = 0; kt < KT; kt++) {
        cp_wait0();
        __syncthreads();

        if (kt + 1 < KT) {
            int nb = (kt + 1) & 1;
            uint32_t ka = (uint32_t)(kt + 1) * (BK * 4);
            uint32_t kb = (uint32_t)(kt + 1) * (BK * H * 4);
#pragma unroll
            for (int i = 0; i < 4; i++) cp16(As + nb * BM * ASTRIDE + adst[i], Ap + aoff[i] + ka);
#pragma unroll
            for (int i = 0; i < 4; i++) cp16(Bs + nb * BK * DBSTRIDE + bdst[i], Bp + boff[i] + kb);
            cp_commit();
        }

        const uint32_t* Ac = As + (kt & 1) * BM * ASTRIDE;
        const uint32_t* Bc = Bs + (kt & 1) * BK * DBSTRIDE;

#pragma unroll
        for (int ks = 0; ks < BK / 8; ks++) {
            uint32_t af[2][4], bf[8][2];
#pragma unroll
            for (int mf = 0; mf < 2; mf++) {
                int rb = warp_m * 32 + mf * 16 + g_r;
                af[mf][0] = Ac[rb * ASTRIDE       + ks * 8 + g_c];
                af[mf][1] = Ac[(rb + 8) * ASTRIDE + ks * 8 + g_c];
                af[mf][2] = Ac[rb * ASTRIDE       + ks * 8 + g_c + 4];
                af[mf][3] = Ac[(rb + 8) * ASTRIDE + ks * 8 + g_c + 4];
            }
#pragma unroll
            for (int nf = 0; nf < 8; nf++) {
                int cb = warp_n * 64 + nf * 8 + g_r;
                bf[nf][0] = Bc[(ks * 8 + g_c) * DBSTRIDE     + cb];
                bf[nf][1] = Bc[(ks * 8 + g_c + 4) * DBSTRIDE + cb];
            }
#pragma unroll
            for (int mf = 0; mf < 2; mf++)
#pragma unroll
                for (int nf = 0; nf < 8; nf++)
                    mma_tf32(acc[mf][nf], af[mf], bf[nf]);
        }
    }

    // epilogue
#pragma unroll
    for (int mf = 0; mf < 2; mf++)
#pragma unroll
        for (int nf = 0; nf < 8; nf++)
#pragma unroll
            for (int i = 0; i < 4; i++) {
                int r = warp_m * 32 + mf * 16 + g_r + ((i >= 2) ? 8 : 0);
                int c = warp_n * 64 + nf * 8 + g_c * 2 + (i & 1);
                int gr = row0 + r;
                if (gr < cnt) {
                    if (SHARED) {
                        y[(size_t)gr * H + col0 + c] = acc[mf][nf][i];
                    } else {
                        int   tok = d_tok[job * NTOK + gr];
                        float w   = d_wt[job * NTOK + gr];
                        atomicAdd(&y[(size_t)tok * H + col0 + c], w * acc[mf][nf][i]);
                    }
                }
            }
}

extern "C" void kernel_launch(void* const* d_in, const int* in_sizes, int n_in,
                              void* d_out, int out_size) {
    const float* x   = (const float*)d_in[0];
    const float* gw  = (const float*)d_in[1];
    const float* Wg  = (const float*)d_in[2];
    const float* Wu  = (const float*)d_in[3];
    const float* Wd  = (const float*)d_in[4];
    const float* sWg = (const float*)d_in[5];
    const float* sWu = (const float*)d_in[6];
    const float* sWd = (const float*)d_in[7];
    float* y = (float*)d_out;

    // 1) tf32-round all GEMM inputs in ONE launch (segments contiguous in scratch)
    cvt_all_kernel<<<4096, 256>>>(
        (const float4*)x,  (const float4*)Wg, (const float4*)Wu, (const float4*)Wd,
        (const float4*)sWg, (const float4*)sWu, (const float4*)sWd);

    // 2) routing
    reset_kernel<<<1, 32>>>();
    gate_kernel<<<NTOK / 8, 256>>>(x, gw);

    const int smem_gu = (2 * BM * ASTRIDE + 4 * BK * BSTRIDE) * 4;    // 73728
    const int smem_dn = (2 * BM * ASTRIDE + 2 * BK * DBSTRIDE) * 4;   // 71680
    cudaFuncSetAttribute(gateup_kernel,      cudaFuncAttributeMaxDynamicSharedMemorySize, smem_gu);
    cudaFuncSetAttribute(down_kernel<true>,  cudaFuncAttributeMaxDynamicSharedMemorySize, smem_dn);
    cudaFuncSetAttribute(down_kernel<false>, cudaFuncAttributeMaxDynamicSharedMemorySize, smem_dn);

    // 3) gate+up
    dim3 g1(MSH / BN, NTOK / BM, NJOBS);    // 16 x 16 x 9
    gateup_kernel<<<g1, 256, smem_gu>>>();

    // 4) down: shared writes y fully (plain stores), then routed accumulates on top
    dim3 g2s(H / DBN, NTOK / BM, 1);        // 16 x 16
    down_kernel<true><<<g2s, 256, smem_dn>>>(y);
    dim3 g2r(H / DBN, NTOK / BM, NEXP);     // 16 x 16 x 8
    down_kernel<false><<<g2r, 256, smem_dn>>>(y);
}

// round 7
// speedup vs baseline: 1.5743x; 1.0182x over previous
#include <cuda_runtime.h>
#include <cuda_bf16.h>
#include <cstdint>

// Problem constants
#define H     2048
#define NTOK  2048      // B*S
#define MR    512       // routed intermediate
#define MSH   1024      // shared intermediate
#define NEXP  8
#define NJOBS 9         // 8 routed experts + 1 shared "expert"

// gateup GEMM tiling
#define BM 128
#define BN 64
#define BK 32
#define ASTRIDE 36      // (BK+4) words: conflict-free A fragment loads
#define BSTRIDE 72      // (BN+8) words: conflict-free B fragment loads
#define NSTG 3          // cp.async pipeline stages

// down GEMM tiling (wider N)
#define DBN 128
#define DBSTRIDE 136    // (DBN+8) words, 136 mod 32 = 8 -> conflict-free

// -------- scratch (no mallocs allowed) --------
__device__ int   d_counts[NEXP];
__device__ int   d_tok[NEXP * NTOK];
__device__ float d_wt [NEXP * NTOK];

// one big scratch: tf32-rounded copies of x + all weights (CONTIGUOUS, in
// cvt_all segment order), plus h buffers
#define OFF_XC   ((size_t)0)                              // NTOK*H
#define OFF_WG   (OFF_XC  + (size_t)NTOK * H)             // NEXP*H*MR
#define OFF_WU   (OFF_WG  + (size_t)NEXP * H * MR)
#define OFF_WD   (OFF_WU  + (size_t)NEXP * H * MR)        // NEXP*MR*H
#define OFF_SWG  (OFF_WD  + (size_t)NEXP * MR * H)        // H*MSH
#define OFF_SWU  (OFF_SWG + (size_t)H * MSH)
#define OFF_SWD  (OFF_SWU + (size_t)H * MSH)              // MSH*H
#define OFF_HB   (OFF_SWD + (size_t)MSH * H)              // routed h: NEXP*NTOK*MR
#define OFF_HBS  (OFF_HB  + (size_t)NEXP * NTOK * MR)     // shared h: NTOK*MSH
#define SCRATCH_TOTAL (OFF_HBS + (size_t)NTOK * MSH)

__device__ float d_scratch[SCRATCH_TOTAL];

// cumulative float4 boundaries of the 7 convert segments
#define C0 ((size_t)0)
#define C1 (OFF_WG  / 4)
#define C2 (OFF_WU  / 4)
#define C3 (OFF_WD  / 4)
#define C4 (OFF_SWG / 4)
#define C5 (OFF_SWU / 4)
#define C6 (OFF_SWD / 4)
#define C7 (OFF_HB  / 4)

// -------- helpers --------
__device__ __forceinline__ uint32_t f2tf(float x) {
    uint32_t r;
    asm("cvt.rna.tf32.f32 %0, %1;" : "=r"(r) : "f"(x));
    return r;
}

__device__ __forceinline__ void cp16(void* smem_dst, const void* gmem_src) {
    uint32_t s = (uint32_t)__cvta_generic_to_shared(smem_dst);
    asm volatile("cp.async.cg.shared.global [%0], [%1], 16;\n" :: "r"(s), "l"(gmem_src));
}
__device__ __forceinline__ void cp_commit() {
    asm volatile("cp.async.commit_group;\n");
}
__device__ __forceinline__ void cp_wait0() {
    asm volatile("cp.async.wait_group 0;\n");
}
__device__ __forceinline__ void cp_wait1() {
    asm volatile("cp.async.wait_group 1;\n");
}

__device__ __forceinline__ void mma_tf32(float* c, const uint32_t* a, const uint32_t* b) {
    asm volatile(
        "mma.sync.aligned.m16n8k8.row.col.f32.tf32.tf32.f32 "
        "{%0,%1,%2,%3}, {%4,%5,%6,%7}, {%8,%9}, {%0,%1,%2,%3};\n"
        : "+f"(c[0]), "+f"(c[1]), "+f"(c[2]), "+f"(c[3])
        : "r"(a[0]), "r"(a[1]), "r"(a[2]), "r"(a[3]),
          "r"(b[0]), "r"(b[1]));
}

// -------- kernel A: tf32-round ALL inputs in one launch --------
__global__ void cvt_all_kernel(
    const float4* __restrict__ s0, const float4* __restrict__ s1,
    const float4* __restrict__ s2, const float4* __restrict__ s3,
    const float4* __restrict__ s4, const float4* __restrict__ s5,
    const float4* __restrict__ s6)
{
    float4* out = reinterpret_cast<float4*>(d_scratch);
    const size_t total = C7;
    size_t stride = (size_t)gridDim.x * blockDim.x;
    for (size_t i = (size_t)blockIdx.x * blockDim.x + threadIdx.x; i < total; i += stride) {
        const float4* src; size_t off;
        if      (i < C1) { src = s0; off = i;      }
        else if (i < C2) { src = s1; off = i - C1; }
        else if (i < C3) { src = s2; off = i - C2; }
        else if (i < C4) { src = s3; off = i - C3; }
        else if (i < C5) { src = s4; off = i - C4; }
        else if (i < C6) { src = s5; off = i - C5; }
        else             { src = s6; off = i - C6; }
        float4 v = src[off];
        float4 o;
        o.x = __uint_as_float(f2tf(v.x));
        o.y = __uint_as_float(f2tf(v.y));
        o.z = __uint_as_float(f2tf(v.z));
        o.w = __uint_as_float(f2tf(v.w));
        out[i] = o;
    }
}

// -------- kernel 0: reset routing counts --------
__global__ void reset_kernel() {
    if (threadIdx.x < NEXP) d_counts[threadIdx.x] = 0;
}

// -------- kernel 1: gate logits + top2 + softmax + route lists --------
__global__ void gate_kernel(const float* __restrict__ x, const float* __restrict__ gw) {
    int warp = blockIdx.x * (blockDim.x >> 5) + (threadIdx.x >> 5);
    int lane = threadIdx.x & 31;
    if (warp >= NTOK) return;
    int t = warp;
    const float4* x4 = reinterpret_cast<const float4*>(x + (size_t)t * H);
    const float4* g4 = reinterpret_cast<const float4*>(gw);
    float acc[NEXP];
#pragma unroll
    for (int e = 0; e < NEXP; e++) acc[e] = 0.f;
    for (int i = lane; i < H / 4; i += 32) {
        float4 xv = x4[i];
#pragma unroll
        for (int e = 0; e < NEXP; e++) {
            float4 gv = g4[e * (H / 4) + i];
            acc[e] += xv.x * gv.x + xv.y * gv.y + xv.z * gv.z + xv.w * gv.w;
        }
    }
#pragma unroll
    for (int e = 0; e < NEXP; e++)
#pragma unroll
        for (int o = 16; o; o >>= 1) acc[e] += __shfl_xor_sync(0xffffffffu, acc[e], o);
    if (lane == 0) {
        int i0 = 0; float v0 = acc[0];
#pragma unroll
        for (int e = 1; e < NEXP; e++) if (acc[e] > v0) { v0 = acc[e]; i0 = e; }
        int i1 = -1; float v1 = -1e30f;
#pragma unroll
        for (int e = 0; e < NEXP; e++) if (e != i0 && acc[e] > v1) { v1 = acc[e]; i1 = e; }
        float e1 = __expf(v1 - v0);
        float s  = 1.f + e1;
        float w0 = 1.f / s, w1 = e1 / s;
        int p0 = atomicAdd(&d_counts[i0], 1);
        d_tok[i0 * NTOK + p0] = t; d_wt[i0 * NTOK + p0] = w0;
        int p1 = atomicAdd(&d_counts[i1], 1);
        d_tok[i1 * NTOK + p1] = t; d_wt[i1 * NTOK + p1] = w1;
    }
}

// -------- kernel 2: fused gate+up dual-GEMM + SiLU*u epilogue --------
// 3-stage cp.async ring, wait_group 1: stage kt resident while kt+1 in flight.
__global__ __launch_bounds__(256, 2) void gateup_kernel() {
    const int  job = blockIdx.z;
    const bool sh  = (job == NEXP);
    const int  Mdim = sh ? MSH : MR;
    const int  cnt  = sh ? NTOK : d_counts[job];
    const int  row0 = blockIdx.y * BM;
    const int  col0 = blockIdx.x * BN;
    if (row0 >= cnt || col0 >= Mdim) return;

    const float* xc = d_scratch + OFF_XC;
    const float* Bg = sh ? d_scratch + OFF_SWG : d_scratch + OFF_WG + (size_t)job * H * MR;
    const float* Bu = sh ? d_scratch + OFF_SWU : d_scratch + OFF_WU + (size_t)job * H * MR;

    extern __shared__ uint32_t smp[];
    uint32_t* As  = smp;                            // [NSTG][BM][ASTRIDE]
    uint32_t* Bgs = smp + NSTG * BM * ASTRIDE;      // [NSTG][BK][BSTRIDE]
    uint32_t* Bus = Bgs + NSTG * BK * BSTRIDE;      // [NSTG][BK][BSTRIDE]

    const int tid = threadIdx.x;
    const int lane = tid & 31;
    const int wid = tid >> 5;
    const int warp_m = wid & 3;
    const int warp_n = wid >> 2;
    const int g_r = lane >> 2;
    const int g_c = lane & 3;

    const float* asrc[4]; int adst[4];
#pragma unroll
    for (int i = 0; i < 4; i++) {
        int idx = tid + i * 256;
        int m = idx >> 3, kq = idx & 7;
        int gl = row0 + m; if (gl >= cnt) gl = cnt - 1;
        int tok = sh ? gl : d_tok[job * NTOK + gl];
        asrc[i] = xc + (size_t)tok * H + kq * 4;
        adst[i] = m * ASTRIDE + kq * 4;
    }
    const float* bsrcg[2]; const float* bsrcu[2]; int bdst[2];
#pragma unroll
    for (int i = 0; i < 2; i++) {
        int idx = tid + i * 256;
        int kr = idx >> 4, nq = idx & 15;
        bsrcg[i] = Bg + (size_t)kr * Mdim + col0 + nq * 4;
        bsrcu[i] = Bu + (size_t)kr * Mdim + col0 + nq * 4;
        bdst[i]  = kr * BSTRIDE + nq * 4;
    }

    float accg[2][4][4], accu[2][4][4];
#pragma unroll
    for (int a = 0; a < 2; a++)
#pragma unroll
        for (int b = 0; b < 4; b++)
#pragma unroll
            for (int c = 0; c < 4; c++) { accg[a][b][c] = 0.f; accu[a][b][c] = 0.f; }

    const int KT = H / BK;   // 64

    // prologue: stages 0 and 1 (KT >= 2 always)
#pragma unroll
    for (int s = 0; s < 2; s++) {
        size_t ka = (size_t)s * BK;
        size_t kb = (size_t)s * BK * Mdim;
#pragma unroll
        for (int i = 0; i < 4; i++) cp16(As + s * BM * ASTRIDE + adst[i], asrc[i] + ka);
#pragma unroll
        for (int i = 0; i < 2; i++) {
            cp16(Bgs + s * BK * BSTRIDE + bdst[i], bsrcg[i] + kb);
            cp16(Bus + s * BK * BSTRIDE + bdst[i], bsrcu[i] + kb);
        }
        cp_commit();
    }

    for (int kt = 0; kt < KT; kt++) {
        if (kt < KT - 1) cp_wait1(); else cp_wait0();
        __syncthreads();   // all warps past reads of stage (kt+2)%NSTG's previous life

        if (kt + 2 < KT) {
            int nb = (kt + 2) % NSTG;
            size_t ka = (size_t)(kt + 2) * BK;
            size_t kb = (size_t)(kt + 2) * BK * Mdim;
#pragma unroll
            for (int i = 0; i < 4; i++) cp16(As + nb * BM * ASTRIDE + adst[i], asrc[i] + ka);
#pragma unroll
            for (int i = 0; i < 2; i++) {
                cp16(Bgs + nb * BK * BSTRIDE + bdst[i], bsrcg[i] + kb);
                cp16(Bus + nb * BK * BSTRIDE + bdst[i], bsrcu[i] + kb);
            }
            cp_commit();
        }

        const int st = kt % NSTG;
        const uint32_t* Ac  = As  + st * BM * ASTRIDE;
        const uint32_t* Bgc = Bgs + st * BK * BSTRIDE;
        const uint32_t* Buc = Bus + st * BK * BSTRIDE;

#pragma unroll
        for (int ks = 0; ks < BK / 8; ks++) {
            uint32_t af[2][4], bg[4][2], bu[4][2];
#pragma unroll
            for (int mf = 0; mf < 2; mf++) {
                int rb = warp_m * 32 + mf * 16 + g_r;
                af[mf][0] = Ac[rb * ASTRIDE       + ks * 8 + g_c];
                af[mf][1] = Ac[(rb + 8) * ASTRIDE + ks * 8 + g_c];
                af[mf][2] = Ac[rb * ASTRIDE       + ks * 8 + g_c + 4];
                af[mf][3] = Ac[(rb + 8) * ASTRIDE + ks * 8 + g_c + 4];
            }
#pragma unroll
            for (int nf = 0; nf < 4; nf++) {
                int cb = warp_n * 32 + nf * 8 + g_r;
                bg[nf][0] = Bgc[(ks * 8 + g_c) * BSTRIDE     + cb];
                bg[nf][1] = Bgc[(ks * 8 + g_c + 4) * BSTRIDE + cb];
                bu[nf][0] = Buc[(ks * 8 + g_c) * BSTRIDE     + cb];
                bu[nf][1] = Buc[(ks * 8 + g_c + 4) * BSTRIDE + cb];
            }
#pragma unroll
            for (int mf = 0; mf < 2; mf++)
#pragma unroll
                for (int nf = 0; nf < 4; nf++) {
                    mma_tf32(accg[mf][nf], af[mf], bg[nf]);
                    mma_tf32(accu[mf][nf], af[mf], bu[nf]);
                }
        }
    }

    float* hb = d_scratch + (sh ? OFF_HBS : OFF_HB + (size_t)job * NTOK * MR);
#pragma unroll
    for (int mf = 0; mf < 2; mf++)
#pragma unroll
        for (int nf = 0; nf < 4; nf++)
#pragma unroll
            for (int i = 0; i < 4; i++) {
                int r = warp_m * 32 + mf * 16 + g_r + ((i >= 2) ? 8 : 0);
                int c = warp_n * 32 + nf * 8 + g_c * 2 + (i & 1);
                int gr = row0 + r;
                if (gr < cnt) {
                    float g = accg[mf][nf][i], u = accu[mf][nf][i];
                    float hval = g / (1.f + __expf(-g)) * u;   // silu(g)*u
                    hb[(size_t)gr * Mdim + col0 + c] = __uint_as_float(f2tf(hval));
                }
            }
}

// -------- kernel 3: down-proj, BM=128 x DBN=128 tiles, 3-stage ring --------
template <bool SHARED>
__global__ __launch_bounds__(256, 2) void down_kernel(float* __restrict__ y) {
    const int  job  = SHARED ? 0 : blockIdx.z;
    const int  Kdim = SHARED ? MSH : MR;
    const int  cnt  = SHARED ? NTOK : d_counts[job];
    const int  row0 = blockIdx.y * BM;
    const int  col0 = blockIdx.x * DBN;   // over H
    if (row0 >= cnt) return;

    const char* Bp = (const char*)(SHARED ? d_scratch + OFF_SWD
                                          : d_scratch + OFF_WD + (size_t)job * MR * H);
    const char* Ap = (const char*)(SHARED ? d_scratch + OFF_HBS
                                          : d_scratch + OFF_HB + (size_t)job * NTOK * MR);

    extern __shared__ uint32_t smp[];
    uint32_t* As = smp;                        // [NSTG][BM][ASTRIDE]
    uint32_t* Bs = smp + NSTG * BM * ASTRIDE;  // [NSTG][BK][DBSTRIDE]

    const int tid = threadIdx.x;
    const int lane = tid & 31;
    const int wid = tid >> 5;
    const int warp_m = wid & 3;
    const int warp_n = wid >> 2;
    const int g_r = lane >> 2;
    const int g_c = lane & 3;

    uint32_t aoff[4]; int adst[4];
#pragma unroll
    for (int i = 0; i < 4; i++) {
        int idx = tid + i * 256;
        int m = idx >> 3, kq = idx & 7;
        aoff[i] = (uint32_t)(((row0 + m) * Kdim + kq * 4) * 4);
        adst[i] = m * ASTRIDE + kq * 4;
    }
    uint32_t boff[4]; int bdst[4];
#pragma unroll
    for (int i = 0; i < 4; i++) {
        int idx = tid + i * 256;
        int kr = idx >> 5, nq = idx & 31;
        boff[i] = (uint32_t)((kr * H + col0 + nq * 4) * 4);
        bdst[i] = kr * DBSTRIDE + nq * 4;
    }

    float acc[2][8][4];
#pragma unroll
    for (int a = 0; a < 2; a++)
#pragma unroll
        for (int b = 0; b < 8; b++)
#pragma unroll
            for (int c = 0; c < 4; c++) acc[a][b][c] = 0.f;

    const int KT = Kdim / BK;   // 16 or 32

    // prologue: stages 0 and 1
#pragma unroll
    for (int s = 0; s < 2; s++) {
        uint32_t ka = (uint32_t)s * (BK * 4);
        uint32_t kb = (uint32_t)s * (BK * H * 4);
#pragma unroll
        for (int i = 0; i < 4; i++) cp16(As + s * BM * ASTRIDE + adst[i], Ap + aoff[i] + ka);
#pragma unroll
        for (int i = 0; i < 4; i++) cp16(Bs + s * BK * DBSTRIDE + bdst[i], Bp + boff[i] + kb);
        cp_commit();
    }

    for (int kt = 0; kt < KT; kt++) {
        if (kt < KT - 1) cp_wait1(); else cp_wait0();
        __syncthreads();

        if (kt + 2 < KT) {
            int nb = (kt + 2) % NSTG;
            uint32_t ka = (uint32_t)(kt + 2) * (BK * 4);
            uint32_t kb = (uint32_t)(kt + 2) * (BK * H * 4);
#pragma unroll
            for (int i = 0; i < 4; i++) cp16(As + nb * BM * ASTRIDE + adst[i], Ap + aoff[i] + ka);
#pragma unroll
            for (int i = 0; i < 4; i++) cp16(Bs + nb * BK * DBSTRIDE + bdst[i], Bp + boff[i] + kb);
            cp_commit();
        }

        const int st = kt % NSTG;
        const uint32_t* Ac = As + st * BM * ASTRIDE;
        const uint32_t* Bc = Bs + st * BK * DBSTRIDE;

#pragma unroll
        for (int ks = 0; ks < BK / 8; ks++) {
            uint32_t af[2][4], bf[8][2];
#pragma unroll
            for (int mf = 0; mf < 2; mf++) {
                int rb = warp_m * 32 + mf * 16 + g_r;
                af[mf][0] = Ac[rb * ASTRIDE       + ks * 8 + g_c];
                af[mf][1] = Ac[(rb + 8) * ASTRIDE + ks * 8 + g_c];
                af[mf][2] = Ac[rb * ASTRIDE       + ks * 8 + g_c + 4];
                af[mf][3] = Ac[(rb + 8) * ASTRIDE + ks * 8 + g_c + 4];
            }
#pragma unroll
            for (int nf = 0; nf < 8; nf++) {
                int cb = warp_n * 64 + nf * 8 + g_r;
                bf[nf][0] = Bc[(ks * 8 + g_c) * DBSTRIDE     + cb];
                bf[nf][1] = Bc[(ks * 8 + g_c + 4) * DBSTRIDE + cb];
            }
#pragma unroll
            for (int mf = 0; mf < 2; mf++)
#pragma unroll
                for (int nf = 0; nf < 8; nf++)
                    mma_tf32(acc[mf][nf], af[mf], bf[nf]);
        }
    }

    // epilogue
#pragma unroll
    for (int mf = 0; mf < 2; mf++)
#pragma unroll
        for (int nf = 0; nf < 8; nf++)
#pragma unroll
            for (int i = 0; i < 4; i++) {
                int r = warp_m * 32 + mf * 16 + g_r + ((i >= 2) ? 8 : 0);
                int c = warp_n * 64 + nf * 8 + g_c * 2 + (i & 1);
                int gr = row0 + r;
                if (gr < cnt) {
                    if (SHARED) {
                        y[(size_t)gr * H + col0 + c] = acc[mf][nf][i];
                    } else {
                        int   tok = d_tok[job * NTOK + gr];
                        float w   = d_wt[job * NTOK + gr];
                        atomicAdd(&y[(size_t)tok * H + col0 + c], w * acc[mf][nf][i]);
                    }
                }
            }
}

extern "C" void kernel_launch(void* const* d_in, const int* in_sizes, int n_in,
                              void* d_out, int out_size) {
    const float* x   = (const float*)d_in[0];
    const float* gw  = (const float*)d_in[1];
    const float* Wg  = (const float*)d_in[2];
    const float* Wu  = (const float*)d_in[3];
    const float* Wd  = (const float*)d_in[4];
    const float* sWg = (const float*)d_in[5];
    const float* sWu = (const float*)d_in[6];
    const float* sWd = (const float*)d_in[7];
    float* y = (float*)d_out;

    // 1) tf32-round all GEMM inputs in ONE launch
    cvt_all_kernel<<<4096, 256>>>(
        (const float4*)x,  (const float4*)Wg, (const float4*)Wu, (const float4*)Wd,
        (const float4*)sWg, (const float4*)sWu, (const float4*)sWd);

    // 2) routing
    reset_kernel<<<1, 32>>>();
    gate_kernel<<<NTOK / 8, 256>>>(x, gw);

    const int smem_gu = (NSTG * BM * ASTRIDE + 2 * NSTG * BK * BSTRIDE) * 4;  // 110592
    const int smem_dn = (NSTG * BM * ASTRIDE + NSTG * BK * DBSTRIDE) * 4;     // 107520
    cudaFuncSetAttribute(gateup_kernel,      cudaFuncAttributeMaxDynamicSharedMemorySize, smem_gu);
    cudaFuncSetAttribute(down_kernel<true>,  cudaFuncAttributeMaxDynamicSharedMemorySize, smem_dn);
    cudaFuncSetAttribute(down_kernel<false>, cudaFuncAttributeMaxDynamicSharedMemorySize, smem_dn);

    // 3) gate+up
    dim3 g1(MSH / BN, NTOK / BM, NJOBS);    // 16 x 16 x 9
    gateup_kernel<<<g1, 256, smem_gu>>>();

    // 4) down: shared writes y fully (plain stores), then routed accumulates on top
    dim3 g2s(H / DBN, NTOK / BM, 1);        // 16 x 16
    down_kernel<true><<<g2s, 256, smem_dn>>>(y);
    dim3 g2r(H / DBN, NTOK / BM, NEXP);     // 16 x 16 x 8
    down_kernel<false><<<g2r, 256, smem_dn>>>(y);
}

// round 10
// speedup vs baseline: 2.4177x; 1.5357x over previous
#include <cuda_runtime.h>
#include <cuda_fp16.h>
#include <cstdint>

// Problem constants
#define H     2048
#define NTOK  2048      // B*S
#define MR    512       // routed intermediate
#define MSH   1024      // shared intermediate
#define NEXP  8
#define NJOBS 9

// GEMM tiling (fp16 operands, m16n8k16)
#define BM   128
#define GUBN 64         // gateup N tile (per matrix g/u)
#define DBN  128        // down N tile
#define BKH  64         // K halfs per smem tile (4 x k16 steps)
#define S36  36         // smem row stride in uint32 words (32 half2 + 4 pad)
#define NSTG 3

// -------- scratch (no mallocs allowed) --------
__device__ int   d_counts[NEXP];
__device__ int   d_tok[NEXP * NTOK];
__device__ float d_wt [NEXP * NTOK];

__device__ __half g_xh  [(size_t)NTOK * H];
__device__ __half g_wgT [(size_t)NEXP * MR * H];   // [e][n=MR][k=H]
__device__ __half g_wuT [(size_t)NEXP * MR * H];
__device__ __half g_swgT[(size_t)MSH * H];         // [n=MSH][k=H]
__device__ __half g_swuT[(size_t)MSH * H];
__device__ __half g_wdT [(size_t)NEXP * H * MR];   // [e][n=H][k=MR]
__device__ __half g_swdT[(size_t)H * MSH];         // [n=H][k=MSH]
#define HB_SHOFF ((size_t)NEXP * NTOK * MR)
__device__ __half g_hb[HB_SHOFF + (size_t)NTOK * MSH];

// -------- helpers --------
__device__ __forceinline__ void cp16(void* smem_dst, const void* gmem_src) {
    uint32_t s = (uint32_t)__cvta_generic_to_shared(smem_dst);
    asm volatile("cp.async.cg.shared.global [%0], [%1], 16;\n" :: "r"(s), "l"(gmem_src));
}
__device__ __forceinline__ void cp_commit() { asm volatile("cp.async.commit_group;\n"); }
__device__ __forceinline__ void cp_wait0()  { asm volatile("cp.async.wait_group 0;\n"); }
__device__ __forceinline__ void cp_wait1()  { asm volatile("cp.async.wait_group 1;\n"); }

// m16n8k16 fp16 MMA, fp32 accumulate
__device__ __forceinline__ void mma_f16(float* c, const uint32_t* a, const uint32_t* b) {
    asm volatile(
        "mma.sync.aligned.m16n8k16.row.col.f32.f16.f16.f32 "
        "{%0,%1,%2,%3}, {%4,%5,%6,%7}, {%8,%9}, {%0,%1,%2,%3};\n"
        : "+f"(c[0]), "+f"(c[1]), "+f"(c[2]), "+f"(c[3])
        : "r"(a[0]), "r"(a[1]), "r"(a[2]), "r"(a[3]),
          "r"(b[0]), "r"(b[1]));
}

// -------- kernel A1: transpose+convert all weights to fp16 [N][K] --------
// 32x32 tiles; 30720 blocks total, segment decoded from blockIdx.x.
__global__ void transpose_cvt_kernel(
    const float* __restrict__ Wg,  const float* __restrict__ Wu,
    const float* __restrict__ sWg, const float* __restrict__ sWu,
    const float* __restrict__ Wd,  const float* __restrict__ sWd)
{
    __shared__ alignas(16) __half st[32][40];
    int b = blockIdx.x;
    const float* src; __half* dst; int K, N;
    if (b < 8192)       { int e = b >> 10; b &= 1023; src = Wg  + (size_t)e * H * MR; dst = g_wgT + (size_t)e * MR * H; K = H;   N = MR; }
    else if (b < 16384) { b -= 8192;  int e = b >> 10; b &= 1023; src = Wu + (size_t)e * H * MR; dst = g_wuT + (size_t)e * MR * H; K = H; N = MR; }
    else if (b < 18432) { b -= 16384; src = sWg; dst = g_swgT; K = H;   N = MSH; }
    else if (b < 20480) { b -= 18432; src = sWu; dst = g_swuT; K = H;   N = MSH; }
    else if (b < 28672) { b -= 20480; int e = b >> 10; b &= 1023; src = Wd + (size_t)e * MR * H; dst = g_wdT + (size_t)e * H * MR; K = MR; N = H; }
    else                { b -= 28672; src = sWd; dst = g_swdT; K = MSH; N = H; }

    int tN = N / 32;
    int bk = b / tN, bn = b % tN;
    int t = threadIdx.x;
    int kl = t >> 3;          // 0..31
    int nl = (t & 7) * 4;     // 0..28
    float4 v = *(const float4*)(src + (size_t)(bk * 32 + kl) * N + bn * 32 + nl);
    st[nl + 0][kl] = __float2half_rn(v.x);
    st[nl + 1][kl] = __float2half_rn(v.y);
    st[nl + 2][kl] = __float2half_rn(v.z);
    st[nl + 3][kl] = __float2half_rn(v.w);
    __syncthreads();
    int nr = t >> 3;          // out row (n)
    int kc = (t & 7) * 4;     // out k start
    *(uint2*)(dst + (size_t)(bn * 32 + nr) * K + bk * 32 + kc) = *(uint2*)&st[nr][kc];
}

// -------- kernel A2: x -> fp16 straight copy --------
__global__ void cvt_x_kernel(const float4* __restrict__ x) {
    __half2* d = reinterpret_cast<__half2*>(g_xh);
    const size_t total = (size_t)NTOK * H / 4;
    size_t stride = (size_t)gridDim.x * blockDim.x;
    for (size_t i = (size_t)blockIdx.x * blockDim.x + threadIdx.x; i < total; i += stride) {
        float4 v = x[i];
        d[2 * i]     = __floats2half2_rn(v.x, v.y);
        d[2 * i + 1] = __floats2half2_rn(v.z, v.w);
    }
}

// -------- kernel 0: reset routing counts --------
__global__ void reset_kernel() {
    if (threadIdx.x < NEXP) d_counts[threadIdx.x] = 0;
}

// -------- kernel 1: gate logits + top2 + softmax + route lists --------
__global__ void gate_kernel(const float* __restrict__ x, const float* __restrict__ gw) {
    int warp = blockIdx.x * (blockDim.x >> 5) + (threadIdx.x >> 5);
    int lane = threadIdx.x & 31;
    if (warp >= NTOK) return;
    int t = warp;
    const float4* x4 = reinterpret_cast<const float4*>(x + (size_t)t * H);
    const float4* g4 = reinterpret_cast<const float4*>(gw);
    float acc[NEXP];
#pragma unroll
    for (int e = 0; e < NEXP; e++) acc[e] = 0.f;
    for (int i = lane; i < H / 4; i += 32) {
        float4 xv = x4[i];
#pragma unroll
        for (int e = 0; e < NEXP; e++) {
            float4 gv = g4[e * (H / 4) + i];
            acc[e] += xv.x * gv.x + xv.y * gv.y + xv.z * gv.z + xv.w * gv.w;
        }
    }
#pragma unroll
    for (int e = 0; e < NEXP; e++)
#pragma unroll
        for (int o = 16; o; o >>= 1) acc[e] += __shfl_xor_sync(0xffffffffu, acc[e], o);
    if (lane == 0) {
        int i0 = 0; float v0 = acc[0];
#pragma unroll
        for (int e = 1; e < NEXP; e++) if (acc[e] > v0) { v0 = acc[e]; i0 = e; }
        int i1 = -1; float v1 = -1e30f;
#pragma unroll
        for (int e = 0; e < NEXP; e++) if (e != i0 && acc[e] > v1) { v1 = acc[e]; i1 = e; }
        float e1 = __expf(v1 - v0);
        float s  = 1.f + e1;
        float w0 = 1.f / s, w1 = e1 / s;
        int p0 = atomicAdd(&d_counts[i0], 1);
        d_tok[i0 * NTOK + p0] = t; d_wt[i0 * NTOK + p0] = w0;
        int p1 = atomicAdd(&d_counts[i1], 1);
        d_tok[i1 * NTOK + p1] = t; d_wt[i1 * NTOK + p1] = w1;
    }
}

// -------- kernel 2: fp16 gate+up dual-GEMM + SiLU*u epilogue --------
// A = x fp16 (gathered rows, k-contiguous); B = WgT/WuT [n][k] fp16.
__global__ __launch_bounds__(256, 2) void gateup_kernel() {
    const int  job = blockIdx.z;
    const bool sh  = (job == NEXP);
    const int  Mdim = sh ? MSH : MR;
    const int  cnt  = sh ? NTOK : d_counts[job];
    const int  row0 = blockIdx.y * BM;
    const int  col0 = blockIdx.x * GUBN;
    if (row0 >= cnt || col0 >= Mdim) return;

    const __half* BgT = sh ? g_swgT : g_wgT + (size_t)job * MR * H;
    const __half* BuT = sh ? g_swuT : g_wuT + (size_t)job * MR * H;

    extern __shared__ uint32_t smp[];
    uint32_t* As  = smp;                        // [NSTG][BM*S36]
    uint32_t* Bgs = smp + NSTG * BM * S36;      // [NSTG][GUBN*S36]
    uint32_t* Bus = Bgs + NSTG * GUBN * S36;

    const int tid = threadIdx.x;
    const int lane = tid & 31;
    const int wid = tid >> 5;
    const int warp_m = wid & 3;   // 4 warps on M
    const int warp_n = wid >> 2;  // 2 warps on N
    const int g_r = lane >> 2;
    const int g_c = lane & 3;

    // A: BM x BKH halfs = 1024 x 16B chunks -> 4/thread
    uint32_t aoff[4]; int adst[4];
#pragma unroll
    for (int j = 0; j < 4; j++) {
        int idx = tid + j * 256;
        int m = idx >> 3, kc = idx & 7;
        int gl = row0 + m; if (gl >= cnt) gl = cnt - 1;
        int tok = sh ? gl : d_tok[job * NTOK + gl];
        aoff[j] = (uint32_t)(tok * H + kc * 8);
        adst[j] = m * S36 + kc * 4;
    }
    // B: GUBN x BKH halfs = 512 chunks per matrix -> 2/thread
    uint32_t boff[2]; int bdst[2];
#pragma unroll
    for (int j = 0; j < 2; j++) {
        int idx = tid + j * 256;
        int n = idx >> 3, kc = idx & 7;
        boff[j] = (uint32_t)((col0 + n) * H + kc * 8);
        bdst[j] = n * S36 + kc * 4;
    }

    float accg[2][4][4], accu[2][4][4];
#pragma unroll
    for (int a = 0; a < 2; a++)
#pragma unroll
        for (int b = 0; b < 4; b++)
#pragma unroll
            for (int c = 0; c < 4; c++) { accg[a][b][c] = 0.f; accu[a][b][c] = 0.f; }

    const int KT = H / BKH;   // 32

    // prologue: stages 0,1
#pragma unroll
    for (int s = 0; s < 2; s++) {
        uint32_t adv = (uint32_t)s * BKH;
#pragma unroll
        for (int j = 0; j < 4; j++) cp16(As + s * BM * S36 + adst[j], g_xh + aoff[j] + adv);
#pragma unroll
        for (int j = 0; j < 2; j++) {
            cp16(Bgs + s * GUBN * S36 + bdst[j], BgT + boff[j] + adv);
            cp16(Bus + s * GUBN * S36 + bdst[j], BuT + boff[j] + adv);
        }
        cp_commit();
    }

    for (int kt = 0; kt < KT; kt++) {
        if (kt < KT - 1) cp_wait1(); else cp_wait0();
        __syncthreads();

        if (kt + 2 < KT) {
            int nb = (kt + 2) % NSTG;
            uint32_t adv = (uint32_t)(kt + 2) * BKH;
#pragma unroll
            for (int j = 0; j < 4; j++) cp16(As + nb * BM * S36 + adst[j], g_xh + aoff[j] + adv);
#pragma unroll
            for (int j = 0; j < 2; j++) {
                cp16(Bgs + nb * GUBN * S36 + bdst[j], BgT + boff[j] + adv);
                cp16(Bus + nb * GUBN * S36 + bdst[j], BuT + boff[j] + adv);
            }
            cp_commit();
        }

        const int st = kt % NSTG;
        const uint32_t* Ac  = As  + st * BM * S36;
        const uint32_t* Bgc = Bgs + st * GUBN * S36;
        const uint32_t* Buc = Bus + st * GUBN * S36;

#pragma unroll
        for (int ks = 0; ks < BKH / 16; ks++) {   // 4 x k16
            uint32_t af[2][4], bg[4][2], bu[4][2];
#pragma unroll
            for (int mf = 0; mf < 2; mf++) {
                int rb = warp_m * 32 + mf * 16 + g_r;
                af[mf][0] = Ac[rb * S36       + ks * 8 + g_c];
                af[mf][1] = Ac[(rb + 8) * S36 + ks * 8 + g_c];
                af[mf][2] = Ac[rb * S36       + ks * 8 + g_c + 4];
                af[mf][3] = Ac[(rb + 8) * S36 + ks * 8 + g_c + 4];
            }
#pragma unroll
            for (int nf = 0; nf < 4; nf++) {
                int cb = warp_n * 32 + nf * 8 + g_r;
                bg[nf][0] = Bgc[cb * S36 + ks * 8 + g_c];
                bg[nf][1] = Bgc[cb * S36 + ks * 8 + g_c + 4];
                bu[nf][0] = Buc[cb * S36 + ks * 8 + g_c];
                bu[nf][1] = Buc[cb * S36 + ks * 8 + g_c + 4];
            }
#pragma unroll
            for (int mf = 0; mf < 2; mf++)
#pragma unroll
                for (int nf = 0; nf < 4; nf++) {
                    mma_f16(accg[mf][nf], af[mf], bg[nf]);
                    mma_f16(accu[mf][nf], af[mf], bu[nf]);
                }
        }
    }

    // epilogue: silu(g)*u -> fp16 h (half2 stores, cols 2g_c/2g_c+1 adjacent)
    __half* hb = g_hb + (sh ? HB_SHOFF : (size_t)job * NTOK * MR);
#pragma unroll
    for (int mf = 0; mf < 2; mf++)
#pragma unroll
        for (int nf = 0; nf < 4; nf++) {
            int c0 = col0 + warp_n * 32 + nf * 8 + g_c * 2;
#pragma unroll
            for (int half_r = 0; half_r < 2; half_r++) {
                int r = warp_m * 32 + mf * 16 + g_r + half_r * 8;
                int gr = row0 + r;
                if (gr < cnt) {
                    float g0 = accg[mf][nf][half_r * 2 + 0], u0 = accu[mf][nf][half_r * 2 + 0];
                    float g1 = accg[mf][nf][half_r * 2 + 1], u1 = accu[mf][nf][half_r * 2 + 1];
                    float h0 = g0 / (1.f + __expf(-g0)) * u0;
                    float h1 = g1 / (1.f + __expf(-g1)) * u1;
                    *reinterpret_cast<__half2*>(hb + (size_t)gr * Mdim + c0) =
                        __floats2half2_rn(h0, h1);
                }
            }
        }
}

// -------- kernel 3: fp16 down-proj --------
// SHARED=true: dense shared expert (plain stores); false: routed atomics on top.
template <bool SHARED>
__global__ __launch_bounds__(256, 2) void down_kernel(float* __restrict__ y) {
    const int  job  = SHARED ? 0 : blockIdx.z;
    const int  Kdim = SHARED ? MSH : MR;
    const int  cnt  = SHARED ? NTOK : d_counts[job];
    const int  row0 = blockIdx.y * BM;
    const int  col0 = blockIdx.x * DBN;
    if (row0 >= cnt) return;

    const __half* Bp = SHARED ? g_swdT : g_wdT + (size_t)job * H * MR;  // [n=H][k]
    const __half* Ap = SHARED ? g_hb + HB_SHOFF : g_hb + (size_t)job * NTOK * MR;

    extern __shared__ uint32_t smp[];
    uint32_t* As = smp;                     // [NSTG][BM*S36]
    uint32_t* Bs = smp + NSTG * BM * S36;   // [NSTG][DBN*S36]

    const int tid = threadIdx.x;
    const int lane = tid & 31;
    const int wid = tid >> 5;
    const int warp_m = wid & 3;
    const int warp_n = wid >> 2;
    const int g_r = lane >> 2;
    const int g_c = lane & 3;

    // A: BM x BKH halfs -> 4 chunks/thread
    uint32_t aoff[4]; int adst[4];
#pragma unroll
    for (int j = 0; j < 4; j++) {
        int idx = tid + j * 256;
        int m = idx >> 3, kc = idx & 7;
        aoff[j] = (uint32_t)((row0 + m) * Kdim + kc * 8);
        adst[j] = m * S36 + kc * 4;
    }
    // B: DBN x BKH halfs -> 4 chunks/thread
    uint32_t boff[4]; int bdst[4];
#pragma unroll
    for (int j = 0; j < 4; j++) {
        int idx = tid + j * 256;
        int n = idx >> 3, kc = idx & 7;
        boff[j] = (uint32_t)((col0 + n) * Kdim + kc * 8);
        bdst[j] = n * S36 + kc * 4;
    }

    float acc[2][8][4];
#pragma unroll
    for (int a = 0; a < 2; a++)
#pragma unroll
        for (int b = 0; b < 8; b++)
#pragma unroll
            for (int c = 0; c < 4; c++) acc[a][b][c] = 0.f;

    const int KT = Kdim / BKH;   // 8 routed, 16 shared

#pragma unroll
    for (int s = 0; s < 2; s++) {
        uint32_t adv = (uint32_t)s * BKH;
#pragma unroll
        for (int j = 0; j < 4; j++) cp16(As + s * BM * S36 + adst[j], Ap + aoff[j] + adv);
#pragma unroll
        for (int j = 0; j < 4; j++) cp16(Bs + s * DBN * S36 + bdst[j], Bp + boff[j] + adv);
        cp_commit();
    }

    for (int kt = 0; kt < KT; kt++) {
        if (kt < KT - 1) cp_wait1(); else cp_wait0();
        __syncthreads();

        if (kt + 2 < KT) {
            int nb = (kt + 2) % NSTG;
            uint32_t adv = (uint32_t)(kt + 2) * BKH;
#pragma unroll
            for (int j = 0; j < 4; j++) cp16(As + nb * BM * S36 + adst[j], Ap + aoff[j] + adv);
#pragma unroll
            for (int j = 0; j < 4; j++) cp16(Bs + nb * DBN * S36 + bdst[j], Bp + boff[j] + adv);
            cp_commit();
        }

        const int st = kt % NSTG;
        const uint32_t* Ac = As + st * BM * S36;
        const uint32_t* Bc = Bs + st * DBN * S36;

#pragma unroll
        for (int ks = 0; ks < BKH / 16; ks++) {
            uint32_t af[2][4], bf[8][2];
#pragma unroll
            for (int mf = 0; mf < 2; mf++) {
                int rb = warp_m * 32 + mf * 16 + g_r;
                af[mf][0] = Ac[rb * S36       + ks * 8 + g_c];
                af[mf][1] = Ac[(rb + 8) * S36 + ks * 8 + g_c];
                af[mf][2] = Ac[rb * S36       + ks * 8 + g_c + 4];
                af[mf][3] = Ac[(rb + 8) * S36 + ks * 8 + g_c + 4];
            }
#pragma unroll
            for (int nf = 0; nf < 8; nf++) {
                int cb = warp_n * 64 + nf * 8 + g_r;
                bf[nf][0] = Bc[cb * S36 + ks * 8 + g_c];
                bf[nf][1] = Bc[cb * S36 + ks * 8 + g_c + 4];
            }
#pragma unroll
            for (int mf = 0; mf < 2; mf++)
#pragma unroll
                for (int nf = 0; nf < 8; nf++)
                    mma_f16(acc[mf][nf], af[mf], bf[nf]);
        }
    }

    // epilogue
#pragma unroll
    for (int mf = 0; mf < 2; mf++)
#pragma unroll
        for (int nf = 0; nf < 8; nf++)
#pragma unroll
            for (int i = 0; i < 4; i++) {
                int r = warp_m * 32 + mf * 16 + g_r + ((i >= 2) ? 8 : 0);
                int c = warp_n * 64 + nf * 8 + g_c * 2 + (i & 1);
                int gr = row0 + r;
                if (gr < cnt) {
                    if (SHARED) {
                        y[(size_t)gr * H + col0 + c] = acc[mf][nf][i];
                    } else {
                        int   tok = d_tok[job * NTOK + gr];
                        float w   = d_wt[job * NTOK + gr];
                        atomicAdd(&y[(size_t)tok * H + col0 + c], w * acc[mf][nf][i]);
                    }
                }
            }
}

extern "C" void kernel_launch(void* const* d_in, const int* in_sizes, int n_in,
                              void* d_out, int out_size) {
    const float* x   = (const float*)d_in[0];
    const float* gw  = (const float*)d_in[1];
    const float* Wg  = (const float*)d_in[2];
    const float* Wu  = (const float*)d_in[3];
    const float* Wd  = (const float*)d_in[4];
    const float* sWg = (const float*)d_in[5];
    const float* sWu = (const float*)d_in[6];
    const float* sWd = (const float*)d_in[7];
    float* y = (float*)d_out;

    // 1) prep: weight transposes -> fp16 [N][K]; x -> fp16
    transpose_cvt_kernel<<<30720, 256>>>(Wg, Wu, sWg, sWu, Wd, sWd);
    cvt_x_kernel<<<4096, 256>>>((const float4*)x);

    // 2) routing
    reset_kernel<<<1, 32>>>();
    gate_kernel<<<NTOK / 8, 256>>>(x, gw);

    const int smem_gu = NSTG * (BM * S36 + 2 * GUBN * S36) * 4;   // 110592
    const int smem_dn = NSTG * (BM * S36 + DBN * S36) * 4;        // 110592
    cudaFuncSetAttribute(gateup_kernel,      cudaFuncAttributeMaxDynamicSharedMemorySize, smem_gu);
    cudaFuncSetAttribute(down_kernel<true>,  cudaFuncAttributeMaxDynamicSharedMemorySize, smem_dn);
    cudaFuncSetAttribute(down_kernel<false>, cudaFuncAttributeMaxDynamicSharedMemorySize, smem_dn);

    // 3) gate+up (fp16 tensor path)
    dim3 g1(MSH / GUBN, NTOK / BM, NJOBS);   // 16 x 16 x 9
    gateup_kernel<<<g1, 256, smem_gu>>>();

    // 4) down: shared writes y fully, routed accumulates on top
    dim3 g2s(H / DBN, NTOK / BM, 1);
    down_kernel<true><<<g2s, 256, smem_dn>>>(y);
    dim3 g2r(H / DBN, NTOK / BM, NEXP);
    down_kernel<false><<<g2r, 256, smem_dn>>>(y);
}